// round 5
// baseline (speedup 1.0000x reference)
#include <cuda_runtime.h>
#include <cuda_bf16.h>
#include <float.h>

#define N_NODES 20000
#define N_EDGES 320000
#define ET      340000
#define IN_CH   512
#define HID     128
#define HEADS   4
#define F1      512
#define OUT_CH  30
#define NEG_SLOPE 0.2f

__device__ float g_h1[N_NODES * F1];
__device__ float g_agg1[N_NODES * F1];
__device__ float g_alS1[N_NODES * HEADS];
__device__ float g_alD1[N_NODES * HEADS];
__device__ float g_zpre[N_NODES * OUT_CH];
__device__ float g_alS2[N_NODES];
__device__ float g_alD2[N_NODES];
__device__ int   g_rowptr[N_NODES + 1];
__device__ int   g_cursor[N_NODES];
__device__ int   g_csr_src[ET];

__device__ __forceinline__ void edge_endpoints(int e, const int* __restrict__ ei,
                                               int& src, int& dst) {
    if (e < N_EDGES) { src = ei[e]; dst = ei[N_EDGES + e]; }
    else { src = e - N_EDGES; dst = src; }
}

__device__ __forceinline__ void ffma2(unsigned long long& acc,
                                      unsigned long long a, unsigned long long b) {
    asm("fma.rn.f32x2 %0, %1, %2, %0;" : "+l"(acc) : "l"(a), "l"(b));
}
__device__ __forceinline__ void upk2(unsigned long long v, float& lo, float& hi) {
    asm("mov.b64 {%0, %1}, %2;" : "=f"(lo), "=f"(hi) : "l"(v));
}

// ================= CSR build =================
__global__ void k_zero_rowptr() {
    int i = blockIdx.x * blockDim.x + threadIdx.x;
    if (i <= N_NODES) g_rowptr[i] = 0;
}
__global__ void k_count(const int* __restrict__ ei) {
    int e = blockIdx.x * blockDim.x + threadIdx.x;
    if (e >= ET) return;
    int src, dst; edge_endpoints(e, ei, src, dst);
    (void)src;
    atomicAdd(&g_rowptr[dst + 1], 1);
}
__global__ void k_scan() {
    __shared__ int s[1024];
    __shared__ int carry;
    int tid = threadIdx.x;
    if (tid == 0) carry = 0;
    __syncthreads();
    for (int base = 0; base <= N_NODES; base += 1024) {
        int i = base + tid;
        int v = (i <= N_NODES) ? g_rowptr[i] : 0;
        s[tid] = v;
        __syncthreads();
        #pragma unroll
        for (int off = 1; off < 1024; off <<= 1) {
            int t = (tid >= off) ? s[tid - off] : 0;
            __syncthreads();
            s[tid] += t;
            __syncthreads();
        }
        int out = s[tid] + carry;
        if (i <= N_NODES) {
            g_rowptr[i] = out;
            if (i < N_NODES) g_cursor[i] = out;
        }
        __syncthreads();
        if (tid == 1023) carry = out;
        __syncthreads();
    }
}
__global__ void k_scatter(const int* __restrict__ ei) {
    int e = blockIdx.x * blockDim.x + threadIdx.x;
    if (e >= ET) return;
    int src, dst; edge_endpoints(e, ei, src, dst);
    int pos = atomicAdd(&g_cursor[dst], 1);
    g_csr_src[pos] = src;
}

// ================= GEMM1: 128x128 tile, 8x8/thread, k-paired FFMA2, prefetch =================
#define BM 128
#define BN 128
#define BK 16
__global__ __launch_bounds__(256, 1)
void k_sgemm8(const float* __restrict__ A, const float* __restrict__ B,
              float* __restrict__ C, int M, int N, int K) {
    __shared__ unsigned long long As2[BK / 2][BM];
    __shared__ unsigned long long Bs2[BK / 2][BN];
    const int tid = threadIdx.x;
    const int tr = tid >> 4;
    const int tc = tid & 15;
    const int rowBase = blockIdx.y * BM;
    const int colBase = blockIdx.x * BN;

    unsigned long long acc[8][8];
    #pragma unroll
    for (int i = 0; i < 8; i++)
        #pragma unroll
        for (int j = 0; j < 8; j++) acc[i][j] = 0ull;

    float4 pa[2], pb[2];
    #pragma unroll
    for (int t = 0; t < 2; t++) {
        int i = tid * 2 + t;
        int r = i >> 2, c = (i & 3) * 4;
        int gr = rowBase + r;
        pa[t] = (gr < M) ? *(const float4*)&A[(size_t)gr * K + c]
                         : make_float4(0.f, 0.f, 0.f, 0.f);
        int k = i >> 5, cb = (i & 31) * 4;
        pb[t] = *(const float4*)&B[(size_t)k * N + colBase + cb];
    }

    for (int k0 = 0; k0 < K; k0 += BK) {
        // stage prefetched tiles into smem (k-paired layout)
        #pragma unroll
        for (int t = 0; t < 2; t++) {
            int i = tid * 2 + t;
            int r = i >> 2, c = (i & 3) * 4;
            *reinterpret_cast<float2*>(&As2[(c >> 1)][r])     = make_float2(pa[t].x, pa[t].y);
            *reinterpret_cast<float2*>(&As2[(c >> 1) + 1][r]) = make_float2(pa[t].z, pa[t].w);
            int k = i >> 5, cb = (i & 31) * 4;
            float* bs = reinterpret_cast<float*>(&Bs2[k >> 1][0]);
            int half = k & 1;
            bs[(cb + 0) * 2 + half] = pb[t].x;
            bs[(cb + 1) * 2 + half] = pb[t].y;
            bs[(cb + 2) * 2 + half] = pb[t].z;
            bs[(cb + 3) * 2 + half] = pb[t].w;
        }
        __syncthreads();
        // prefetch next tile (global loads overlap compute)
        if (k0 + BK < K) {
            #pragma unroll
            for (int t = 0; t < 2; t++) {
                int i = tid * 2 + t;
                int r = i >> 2, c = (i & 3) * 4;
                int gr = rowBase + r;
                pa[t] = (gr < M) ? *(const float4*)&A[(size_t)gr * K + k0 + BK + c]
                                 : make_float4(0.f, 0.f, 0.f, 0.f);
                int k = i >> 5, cb = (i & 31) * 4;
                pb[t] = *(const float4*)&B[(size_t)(k0 + BK + k) * N + colBase + cb];
            }
        }
        #pragma unroll
        for (int k2 = 0; k2 < BK / 2; k2++) {
            unsigned long long ap[8], bp[8];
            #pragma unroll
            for (int i2 = 0; i2 < 4; i2++) {
                ulonglong2 a = *reinterpret_cast<const ulonglong2*>(&As2[k2][tr * 8 + i2 * 2]);
                ap[i2 * 2] = a.x; ap[i2 * 2 + 1] = a.y;
            }
            #pragma unroll
            for (int j2 = 0; j2 < 4; j2++) {
                ulonglong2 b = *reinterpret_cast<const ulonglong2*>(&Bs2[k2][tc * 8 + j2 * 2]);
                bp[j2 * 2] = b.x; bp[j2 * 2 + 1] = b.y;
            }
            #pragma unroll
            for (int i = 0; i < 8; i++)
                #pragma unroll
                for (int j = 0; j < 8; j++) ffma2(acc[i][j], ap[i], bp[j]);
        }
        __syncthreads();
    }
    #pragma unroll
    for (int i = 0; i < 8; i++) {
        int gr = rowBase + tr * 8 + i;
        if (gr >= M) continue;
        float o[8];
        #pragma unroll
        for (int j = 0; j < 8; j++) {
            float lo, hi; upk2(acc[i][j], lo, hi);
            o[j] = lo + hi;
        }
        *(float4*)&C[(size_t)gr * N + colBase + tc * 8 + 0] = *(float4*)&o[0];
        *(float4*)&C[(size_t)gr * N + colBase + tc * 8 + 4] = *(float4*)&o[4];
    }
}

// ================= layer 1 attention logits per node =================
__global__ void k_logits1(const float* __restrict__ aS, const float* __restrict__ aD) {
    int n = blockIdx.x;
    int w = threadIdx.x >> 5, lane = threadIdx.x & 31;
    const float* hr = g_h1 + (size_t)n * F1 + w * HID;
    const float* av = aS + w * HID;
    const float* dv = aD + w * HID;
    float s = 0.f, d = 0.f;
    #pragma unroll
    for (int i = 0; i < 4; i++) {
        float hv = hr[lane + i * 32];
        s = fmaf(hv, av[lane + i * 32], s);
        d = fmaf(hv, dv[lane + i * 32], d);
    }
    #pragma unroll
    for (int o = 16; o > 0; o >>= 1) {
        s += __shfl_down_sync(0xffffffffu, s, o);
        d += __shfl_down_sync(0xffffffffu, d, o);
    }
    if (lane == 0) { g_alS1[n * HEADS + w] = s; g_alD1[n * HEADS + w] = d; }
}

// ================= layer 1 fused softmax + aggregate + bias + ELU =================
__global__ __launch_bounds__(256)
void k_agg1(const float* __restrict__ b1) {
    int warp = (blockIdx.x * blockDim.x + threadIdx.x) >> 5;
    int lane = threadIdx.x & 31;
    if (warp >= N_NODES) return;
    int n = warp;
    int beg = g_rowptr[n], end = g_rowptr[n + 1];
    float4 ad = *(const float4*)&g_alD1[n * 4];

    float4 den = make_float4(0.f, 0.f, 0.f, 0.f);
    for (int e = beg + lane; e < end; e += 32) {
        int src = g_csr_src[e];
        float4 s = *(const float4*)&g_alS1[src * 4];
        float v;
        v = s.x + ad.x; den.x += __expf(v > 0.f ? v : NEG_SLOPE * v);
        v = s.y + ad.y; den.y += __expf(v > 0.f ? v : NEG_SLOPE * v);
        v = s.z + ad.z; den.z += __expf(v > 0.f ? v : NEG_SLOPE * v);
        v = s.w + ad.w; den.w += __expf(v > 0.f ? v : NEG_SLOPE * v);
    }
    #pragma unroll
    for (int o = 16; o > 0; o >>= 1) {
        den.x += __shfl_xor_sync(0xffffffffu, den.x, o);
        den.y += __shfl_xor_sync(0xffffffffu, den.y, o);
        den.z += __shfl_xor_sync(0xffffffffu, den.z, o);
        den.w += __shfl_xor_sync(0xffffffffu, den.w, o);
    }
    float r0 = 1.f / den.x, r1 = 1.f / den.y, r2 = 1.f / den.z, r3 = 1.f / den.w;

    float4 a0 = make_float4(0.f, 0.f, 0.f, 0.f);
    float4 a1 = a0, a2 = a0, a3 = a0;
    for (int e = beg; e < end; e++) {
        int src = g_csr_src[e];
        float4 s = *(const float4*)&g_alS1[src * 4];
        float v, w0, w1, w2, w3;
        v = s.x + ad.x; w0 = __expf(v > 0.f ? v : NEG_SLOPE * v) * r0;
        v = s.y + ad.y; w1 = __expf(v > 0.f ? v : NEG_SLOPE * v) * r1;
        v = s.z + ad.z; w2 = __expf(v > 0.f ? v : NEG_SLOPE * v) * r2;
        v = s.w + ad.w; w3 = __expf(v > 0.f ? v : NEG_SLOPE * v) * r3;
        const float4* hp = (const float4*)&g_h1[(size_t)src * F1];
        float4 h;
        h = hp[lane];      a0.x = fmaf(w0, h.x, a0.x); a0.y = fmaf(w0, h.y, a0.y); a0.z = fmaf(w0, h.z, a0.z); a0.w = fmaf(w0, h.w, a0.w);
        h = hp[32 + lane]; a1.x = fmaf(w1, h.x, a1.x); a1.y = fmaf(w1, h.y, a1.y); a1.z = fmaf(w1, h.z, a1.z); a1.w = fmaf(w1, h.w, a1.w);
        h = hp[64 + lane]; a2.x = fmaf(w2, h.x, a2.x); a2.y = fmaf(w2, h.y, a2.y); a2.z = fmaf(w2, h.z, a2.z); a2.w = fmaf(w2, h.w, a2.w);
        h = hp[96 + lane]; a3.x = fmaf(w3, h.x, a3.x); a3.y = fmaf(w3, h.y, a3.y); a3.z = fmaf(w3, h.z, a3.z); a3.w = fmaf(w3, h.w, a3.w);
    }
    float* outp = &g_agg1[(size_t)n * F1];
    float4 acc[4] = { a0, a1, a2, a3 };
    #pragma unroll
    for (int h = 0; h < 4; h++) {
        float4 bb = *(const float4*)&b1[h * HID + lane * 4];
        float4 v = acc[h];
        v.x += bb.x; v.y += bb.y; v.z += bb.z; v.w += bb.w;
        v.x = v.x > 0.f ? v.x : expm1f(v.x);
        v.y = v.y > 0.f ? v.y : expm1f(v.y);
        v.z = v.z > 0.f ? v.z : expm1f(v.z);
        v.w = v.w > 0.f ? v.w : expm1f(v.w);
        *(float4*)&outp[h * HID + lane * 4] = v;
    }
}

// ================= gemm2 tiled: g_zpre = g_agg1[M,512] @ W2[512,30] =================
__global__ __launch_bounds__(256, 2)
void k_gemm2t(const float* __restrict__ W2) {
    __shared__ unsigned long long As2[BK / 2][BM];
    __shared__ unsigned long long Bs2[BK / 2][32];
    const int tid = threadIdx.x;
    const int tr = tid >> 4;
    const int tc = tid & 15;
    const int rowBase = blockIdx.x * BM;

    unsigned long long acc[8][2];
    #pragma unroll
    for (int i = 0; i < 8; i++) { acc[i][0] = 0ull; acc[i][1] = 0ull; }

    for (int k0 = 0; k0 < F1; k0 += BK) {
        #pragma unroll
        for (int t = 0; t < 2; t++) {
            int i = tid * 2 + t;
            int r = i >> 2;
            int c = (i & 3) * 4;
            int gr = rowBase + r;
            float4 v = make_float4(0.f, 0.f, 0.f, 0.f);
            if (gr < N_NODES) v = *(const float4*)&g_agg1[(size_t)gr * F1 + k0 + c];
            *reinterpret_cast<float2*>(&As2[(c >> 1)][r])     = make_float2(v.x, v.y);
            *reinterpret_cast<float2*>(&As2[(c >> 1) + 1][r]) = make_float2(v.z, v.w);
        }
        {
            #pragma unroll
            for (int t = 0; t < 2; t++) {
                int idx = tid * 2 + t;
                int k = idx >> 5;
                int c = idx & 31;
                float v = (c < OUT_CH) ? W2[(size_t)(k0 + k) * OUT_CH + c] : 0.f;
                float* bs = reinterpret_cast<float*>(&Bs2[k >> 1][0]);
                bs[c * 2 + (k & 1)] = v;
            }
        }
        __syncthreads();
        #pragma unroll
        for (int k2 = 0; k2 < BK / 2; k2++) {
            unsigned long long ap[8], bp[2];
            #pragma unroll
            for (int i2 = 0; i2 < 4; i2++) {
                ulonglong2 a = *reinterpret_cast<const ulonglong2*>(&As2[k2][tr * 8 + i2 * 2]);
                ap[i2 * 2] = a.x; ap[i2 * 2 + 1] = a.y;
            }
            {
                ulonglong2 b = *reinterpret_cast<const ulonglong2*>(&Bs2[k2][tc * 2]);
                bp[0] = b.x; bp[1] = b.y;
            }
            #pragma unroll
            for (int i = 0; i < 8; i++) {
                ffma2(acc[i][0], ap[i], bp[0]);
                ffma2(acc[i][1], ap[i], bp[1]);
            }
        }
        __syncthreads();
    }
    #pragma unroll
    for (int i = 0; i < 8; i++) {
        int gr = rowBase + tr * 8 + i;
        if (gr >= N_NODES) continue;
        #pragma unroll
        for (int j = 0; j < 2; j++) {
            int c = tc * 2 + j;
            if (c < OUT_CH) {
                float lo, hi; upk2(acc[i][j], lo, hi);
                g_zpre[(size_t)gr * OUT_CH + c] = lo + hi;
            }
        }
    }
}

// ================= logits2: warp per node =================
__global__ __launch_bounds__(256)
void k_logits2(const float* __restrict__ aS2, const float* __restrict__ aD2) {
    int warp = (blockIdx.x * blockDim.x + threadIdx.x) >> 5;
    int lane = threadIdx.x & 31;
    if (warp >= N_NODES) return;
    float z = (lane < OUT_CH) ? g_zpre[warp * OUT_CH + lane] : 0.f;
    float ps = (lane < OUT_CH) ? z * aS2[lane] : 0.f;
    float pd = (lane < OUT_CH) ? z * aD2[lane] : 0.f;
    #pragma unroll
    for (int o = 16; o > 0; o >>= 1) {
        ps += __shfl_down_sync(0xffffffffu, ps, o);
        pd += __shfl_down_sync(0xffffffffu, pd, o);
    }
    if (lane == 0) { g_alS2[warp] = ps; g_alD2[warp] = pd; }
}

// ================= layer 2 fused softmax + aggregate + bias -> outZ =================
__global__ __launch_bounds__(256)
void k_agg2(const float* __restrict__ b2, float* __restrict__ outZ) {
    int warp = (blockIdx.x * blockDim.x + threadIdx.x) >> 5;
    int lane = threadIdx.x & 31;
    if (warp >= N_NODES) return;
    int n = warp;
    int beg = g_rowptr[n], end = g_rowptr[n + 1];
    float ad = g_alD2[n];

    float den = 0.f;
    for (int e = beg + lane; e < end; e += 32) {
        int src = g_csr_src[e];
        float v = g_alS2[src] + ad;
        den += __expf(v > 0.f ? v : NEG_SLOPE * v);
    }
    #pragma unroll
    for (int o = 16; o > 0; o >>= 1) den += __shfl_xor_sync(0xffffffffu, den, o);
    float rden = 1.f / den;

    float acc = 0.f;
    for (int e = beg; e < end; e++) {
        int src = g_csr_src[e];
        float v = g_alS2[src] + ad;
        float alpha = __expf(v > 0.f ? v : NEG_SLOPE * v) * rden;
        if (lane < OUT_CH) acc = fmaf(alpha, g_zpre[src * OUT_CH + lane], acc);
    }
    if (lane < OUT_CH) outZ[n * OUT_CH + lane] = acc + b2[lane];
}

// ================= decoder tiled: out = z[M,30] @ Wd[30,512] + bd =================
#define DBN 64
__global__ __launch_bounds__(256, 2)
void k_decodert(const float* __restrict__ Wd, const float* __restrict__ bd,
                float* __restrict__ out, const float* __restrict__ z) {
    __shared__ float As[32][BM + 4];
    __shared__ float Bs[32][DBN];
    const int tid = threadIdx.x;
    const int tr = tid >> 4;
    const int tc = tid & 15;
    const int rowBase = blockIdx.y * BM;
    const int colBase = blockIdx.x * DBN;

    for (int idx = tid; idx < BM * 32; idx += 256) {
        int r = idx >> 5;
        int k = idx & 31;
        int gr = rowBase + r;
        float v = 0.f;
        if (k < OUT_CH && gr < N_NODES) v = z[(size_t)gr * OUT_CH + k];
        As[k][r] = v;
    }
    for (int idx = tid; idx < 32 * DBN; idx += 256) {
        int k = idx >> 6;
        int c = idx & 63;
        Bs[k][c] = (k < OUT_CH) ? Wd[(size_t)k * IN_CH + colBase + c] : 0.f;
    }
    __syncthreads();

    float acc[8][4];
    {
        float4 bb = *(const float4*)&bd[colBase + tc * 4];
        #pragma unroll
        for (int i = 0; i < 8; i++) {
            acc[i][0] = bb.x; acc[i][1] = bb.y; acc[i][2] = bb.z; acc[i][3] = bb.w;
        }
    }
    #pragma unroll
    for (int k = 0; k < OUT_CH; k++) {
        float a[8], b[4];
        #pragma unroll
        for (int i = 0; i < 8; i += 4)
            *(float4*)&a[i] = *(const float4*)&As[k][tr * 8 + i];
        *(float4*)&b[0] = *(const float4*)&Bs[k][tc * 4];
        #pragma unroll
        for (int i = 0; i < 8; i++)
            #pragma unroll
            for (int j = 0; j < 4; j++) acc[i][j] = fmaf(a[i], b[j], acc[i][j]);
    }
    #pragma unroll
    for (int i = 0; i < 8; i++) {
        int gr = rowBase + tr * 8 + i;
        if (gr >= N_NODES) continue;
        *(float4*)&out[(size_t)gr * IN_CH + colBase + tc * 4] = *(float4*)&acc[i][0];
    }
}

extern "C" void kernel_launch(void* const* d_in, const int* in_sizes, int n_in,
                              void* d_out, int out_size) {
    const float* x   = (const float*)d_in[0];
    const int*   ei  = (const int*)d_in[1];
    const float* W1  = (const float*)d_in[2];
    const float* aS1 = (const float*)d_in[3];
    const float* aD1 = (const float*)d_in[4];
    const float* b1  = (const float*)d_in[5];
    const float* W2  = (const float*)d_in[6];
    const float* aS2 = (const float*)d_in[7];
    const float* aD2 = (const float*)d_in[8];
    const float* b2  = (const float*)d_in[9];
    const float* Wd  = (const float*)d_in[10];
    const float* bd  = (const float*)d_in[11];
    (void)in_sizes; (void)n_in; (void)out_size;

    float* out  = (float*)d_out;
    float* outZ = out + (size_t)N_NODES * IN_CH;

    static cudaStream_t s2 = nullptr;
    static cudaEvent_t evFork = nullptr, evJoin = nullptr;
    if (s2 == nullptr) {
        cudaStreamCreateWithFlags(&s2, cudaStreamNonBlocking);
        cudaEventCreateWithFlags(&evFork, cudaEventDisableTiming);
        cudaEventCreateWithFlags(&evJoin, cudaEventDisableTiming);
    }

    // fork: CSR build on s2, concurrent with GEMM1 + logits1
    cudaEventRecord(evFork, 0);
    cudaStreamWaitEvent(s2, evFork, 0);
    k_zero_rowptr<<<(N_NODES + 1 + 255) / 256, 256, 0, s2>>>();
    k_count<<<(ET + 255) / 256, 256, 0, s2>>>(ei);
    k_scan<<<1, 1024, 0, s2>>>();
    k_scatter<<<(ET + 255) / 256, 256, 0, s2>>>(ei);
    cudaEventRecord(evJoin, s2);

    {
        float* C; cudaGetSymbolAddress((void**)&C, g_h1);
        dim3 grid(F1 / BN, (N_NODES + BM - 1) / BM);
        k_sgemm8<<<grid, 256>>>(x, W1, C, N_NODES, F1, IN_CH);
    }
    k_logits1<<<N_NODES, 128>>>(aS1, aD1);

    // join: agg1 needs the CSR
    cudaStreamWaitEvent(0, evJoin, 0);

    k_agg1<<<(N_NODES * 32 + 255) / 256, 256>>>(b1);

    k_gemm2t<<<(N_NODES + BM - 1) / BM, 256>>>(W2);
    k_logits2<<<(N_NODES * 32 + 255) / 256, 256>>>(aS2, aD2);
    k_agg2<<<(N_NODES * 32 + 255) / 256, 256>>>(b2, outZ);

    {
        dim3 grid(IN_CH / DBN, (N_NODES + BM - 1) / BM);
        k_decodert<<<grid, 256>>>(Wd, bd, out, outZ);
    }
}

// round 7
// speedup vs baseline: 1.2027x; 1.2027x over previous
#include <cuda_runtime.h>
#include <cuda_bf16.h>
#include <cstdint>
#include <float.h>

#define N_NODES 20000
#define N_EDGES 320000
#define ET      340000
#define IN_CH   512
#define HID     128
#define HEADS   4
#define F1      512
#define OUT_CH  30
#define NEG_SLOPE 0.2f

__device__ float g_h1[N_NODES * F1];
__device__ float g_agg1[N_NODES * F1];
__device__ float g_alS1[N_NODES * HEADS];
__device__ float g_alD1[N_NODES * HEADS];
__device__ float g_zpre[N_NODES * OUT_CH];
__device__ float g_alS2[N_NODES];
__device__ float g_alD2[N_NODES];
__device__ int   g_rowptr[N_NODES + 1];
__device__ int   g_cursor[N_NODES];
__device__ int   g_csr_src[ET];

__device__ __forceinline__ void edge_endpoints(int e, const int* __restrict__ ei,
                                               int& src, int& dst) {
    if (e < N_EDGES) { src = ei[e]; dst = ei[N_EDGES + e]; }
    else { src = e - N_EDGES; dst = src; }
}

__device__ __forceinline__ void ffma2(unsigned long long& acc,
                                      unsigned long long a, unsigned long long b) {
    asm("fma.rn.f32x2 %0, %1, %2, %0;" : "+l"(acc) : "l"(a), "l"(b));
}
__device__ __forceinline__ void upk2(unsigned long long v, float& lo, float& hi) {
    asm("mov.b64 {%0, %1}, %2;" : "=f"(lo), "=f"(hi) : "l"(v));
}
__device__ __forceinline__ void cp_async8(void* smem_dst, const void* gmem_src, int src_sz) {
    unsigned int s = (unsigned int)__cvta_generic_to_shared(smem_dst);
    asm volatile("cp.async.ca.shared.global [%0], [%1], 8, %2;"
                 :: "r"(s), "l"(gmem_src), "r"(src_sz));
}

// ================= CSR build =================
__global__ void k_zero_rowptr() {
    int i = blockIdx.x * blockDim.x + threadIdx.x;
    if (i <= N_NODES) g_rowptr[i] = 0;
}
__global__ void k_count(const int* __restrict__ ei) {
    int e = blockIdx.x * blockDim.x + threadIdx.x;
    if (e >= ET) return;
    int src, dst; edge_endpoints(e, ei, src, dst);
    (void)src;
    atomicAdd(&g_rowptr[dst + 1], 1);
}
__global__ void k_scan() {
    __shared__ int s[1024];
    __shared__ int carry;
    int tid = threadIdx.x;
    if (tid == 0) carry = 0;
    __syncthreads();
    for (int base = 0; base <= N_NODES; base += 1024) {
        int i = base + tid;
        int v = (i <= N_NODES) ? g_rowptr[i] : 0;
        s[tid] = v;
        __syncthreads();
        #pragma unroll
        for (int off = 1; off < 1024; off <<= 1) {
            int t = (tid >= off) ? s[tid - off] : 0;
            __syncthreads();
            s[tid] += t;
            __syncthreads();
        }
        int out = s[tid] + carry;
        if (i <= N_NODES) {
            g_rowptr[i] = out;
            if (i < N_NODES) g_cursor[i] = out;
        }
        __syncthreads();
        if (tid == 1023) carry = out;
        __syncthreads();
    }
}
__global__ void k_scatter(const int* __restrict__ ei) {
    int e = blockIdx.x * blockDim.x + threadIdx.x;
    if (e >= ET) return;
    int src, dst; edge_endpoints(e, ei, src, dst);
    int pos = atomicAdd(&g_cursor[dst], 1);
    g_csr_src[pos] = src;
}

// ====== GEMM1: 128x64 tile, 8x4/thread, k-paired FFMA2, cp.async double-buffer ======
#define BM 128
#define BN 64
#define BK 16
__global__ __launch_bounds__(256, 2)
void k_sgemm(const float* __restrict__ A, const float* __restrict__ B,
             float* __restrict__ C, int M, int N, int K) {
    __shared__ unsigned long long As2[2][BK / 2][BM];
    __shared__ unsigned long long Bs2[2][BK / 2][BN];
    const int tid = threadIdx.x;
    const int tr = tid >> 4;
    const int tc = tid & 15;
    const int rowBase = blockIdx.y * BM;
    const int colBase = blockIdx.x * BN;

    unsigned long long acc[8][4];
    #pragma unroll
    for (int i = 0; i < 8; i++)
        #pragma unroll
        for (int j = 0; j < 4; j++) acc[i][j] = 0ull;

    const int bk = tid >> 4;           // 0..15 (B k row)
    const int bc = (tid & 15) * 4;     // B cols

    // prologue: async-load A tile 0, register-load B tile 0
    #pragma unroll
    for (int t = 0; t < 4; t++) {
        int idx = tid * 4 + t;
        int r = idx >> 3, k2 = idx & 7;
        int gr = rowBase + r;
        cp_async8(&As2[0][k2][r], &A[(size_t)gr * K + 2 * k2], (gr < M) ? 8 : 0);
    }
    asm volatile("cp.async.commit_group;");
    float4 pb = *(const float4*)&B[(size_t)bk * N + colBase + bc];

    const int T = K / BK;
    for (int t = 0; t < T; t++) {
        int cur = t & 1;
        // stage B(t) into smem (k-paired interleave)
        {
            float* bs = reinterpret_cast<float*>(&Bs2[cur][bk >> 1][0]);
            int half = bk & 1;
            bs[(bc + 0) * 2 + half] = pb.x;
            bs[(bc + 1) * 2 + half] = pb.y;
            bs[(bc + 2) * 2 + half] = pb.z;
            bs[(bc + 3) * 2 + half] = pb.w;
        }
        if (t + 1 < T) {
            int k0n = (t + 1) * BK;
            #pragma unroll
            for (int u = 0; u < 4; u++) {
                int idx = tid * 4 + u;
                int r = idx >> 3, k2 = idx & 7;
                int gr = rowBase + r;
                cp_async8(&As2[cur ^ 1][k2][r], &A[(size_t)gr * K + k0n + 2 * k2],
                          (gr < M) ? 8 : 0);
            }
            asm volatile("cp.async.commit_group;");
            pb = *(const float4*)&B[(size_t)(k0n + bk) * N + colBase + bc];
            asm volatile("cp.async.wait_group 1;");
        } else {
            asm volatile("cp.async.wait_group 0;");
        }
        __syncthreads();
        #pragma unroll
        for (int k2 = 0; k2 < BK / 2; k2++) {
            unsigned long long ap[8], bp[4];
            #pragma unroll
            for (int i2 = 0; i2 < 4; i2++) {
                ulonglong2 a = *reinterpret_cast<const ulonglong2*>(&As2[cur][k2][tr * 8 + i2 * 2]);
                ap[i2 * 2] = a.x; ap[i2 * 2 + 1] = a.y;
            }
            {
                ulonglong2 b0 = *reinterpret_cast<const ulonglong2*>(&Bs2[cur][k2][tc * 4]);
                ulonglong2 b1 = *reinterpret_cast<const ulonglong2*>(&Bs2[cur][k2][tc * 4 + 2]);
                bp[0] = b0.x; bp[1] = b0.y; bp[2] = b1.x; bp[3] = b1.y;
            }
            #pragma unroll
            for (int i = 0; i < 8; i++)
                #pragma unroll
                for (int j = 0; j < 4; j++) ffma2(acc[i][j], ap[i], bp[j]);
        }
        __syncthreads();
    }
    #pragma unroll
    for (int i = 0; i < 8; i++) {
        int gr = rowBase + tr * 8 + i;
        if (gr >= M) continue;
        float o[4];
        #pragma unroll
        for (int j = 0; j < 4; j++) {
            float lo, hi; upk2(acc[i][j], lo, hi);
            o[j] = lo + hi;
        }
        *(float4*)&C[(size_t)gr * N + colBase + tc * 4] = *(float4*)&o[0];
    }
}

// ================= layer 1 attention logits per node =================
__global__ void k_logits1(const float* __restrict__ aS, const float* __restrict__ aD) {
    int n = blockIdx.x;
    int w = threadIdx.x >> 5, lane = threadIdx.x & 31;
    const float* hr = g_h1 + (size_t)n * F1 + w * HID;
    const float* av = aS + w * HID;
    const float* dv = aD + w * HID;
    float s = 0.f, d = 0.f;
    #pragma unroll
    for (int i = 0; i < 4; i++) {
        float hv = hr[lane + i * 32];
        s = fmaf(hv, av[lane + i * 32], s);
        d = fmaf(hv, dv[lane + i * 32], d);
    }
    #pragma unroll
    for (int o = 16; o > 0; o >>= 1) {
        s += __shfl_down_sync(0xffffffffu, s, o);
        d += __shfl_down_sync(0xffffffffu, d, o);
    }
    if (lane == 0) { g_alS1[n * HEADS + w] = s; g_alD1[n * HEADS + w] = d; }
}

// ================= layer 1 fused softmax + aggregate + bias + ELU =================
__global__ __launch_bounds__(256)
void k_agg1(const float* __restrict__ b1) {
    int warp = (blockIdx.x * blockDim.x + threadIdx.x) >> 5;
    int lane = threadIdx.x & 31;
    if (warp >= N_NODES) return;
    int n = warp;
    int beg = g_rowptr[n], end = g_rowptr[n + 1];
    float4 ad = *(const float4*)&g_alD1[n * 4];

    float4 den = make_float4(0.f, 0.f, 0.f, 0.f);
    for (int e = beg + lane; e < end; e += 32) {
        int src = g_csr_src[e];
        float4 s = *(const float4*)&g_alS1[src * 4];
        float v;
        v = s.x + ad.x; den.x += __expf(v > 0.f ? v : NEG_SLOPE * v);
        v = s.y + ad.y; den.y += __expf(v > 0.f ? v : NEG_SLOPE * v);
        v = s.z + ad.z; den.z += __expf(v > 0.f ? v : NEG_SLOPE * v);
        v = s.w + ad.w; den.w += __expf(v > 0.f ? v : NEG_SLOPE * v);
    }
    #pragma unroll
    for (int o = 16; o > 0; o >>= 1) {
        den.x += __shfl_xor_sync(0xffffffffu, den.x, o);
        den.y += __shfl_xor_sync(0xffffffffu, den.y, o);
        den.z += __shfl_xor_sync(0xffffffffu, den.z, o);
        den.w += __shfl_xor_sync(0xffffffffu, den.w, o);
    }
    float r0 = 1.f / den.x, r1 = 1.f / den.y, r2 = 1.f / den.z, r3 = 1.f / den.w;

    float4 a0 = make_float4(0.f, 0.f, 0.f, 0.f);
    float4 a1 = a0, a2 = a0, a3 = a0;
    for (int e = beg; e < end; e++) {
        int src = g_csr_src[e];
        float4 s = *(const float4*)&g_alS1[src * 4];
        float v, w0, w1, w2, w3;
        v = s.x + ad.x; w0 = __expf(v > 0.f ? v : NEG_SLOPE * v) * r0;
        v = s.y + ad.y; w1 = __expf(v > 0.f ? v : NEG_SLOPE * v) * r1;
        v = s.z + ad.z; w2 = __expf(v > 0.f ? v : NEG_SLOPE * v) * r2;
        v = s.w + ad.w; w3 = __expf(v > 0.f ? v : NEG_SLOPE * v) * r3;
        const float4* hp = (const float4*)&g_h1[(size_t)src * F1];
        float4 h;
        h = hp[lane];      a0.x = fmaf(w0, h.x, a0.x); a0.y = fmaf(w0, h.y, a0.y); a0.z = fmaf(w0, h.z, a0.z); a0.w = fmaf(w0, h.w, a0.w);
        h = hp[32 + lane]; a1.x = fmaf(w1, h.x, a1.x); a1.y = fmaf(w1, h.y, a1.y); a1.z = fmaf(w1, h.z, a1.z); a1.w = fmaf(w1, h.w, a1.w);
        h = hp[64 + lane]; a2.x = fmaf(w2, h.x, a2.x); a2.y = fmaf(w2, h.y, a2.y); a2.z = fmaf(w2, h.z, a2.z); a2.w = fmaf(w2, h.w, a2.w);
        h = hp[96 + lane]; a3.x = fmaf(w3, h.x, a3.x); a3.y = fmaf(w3, h.y, a3.y); a3.z = fmaf(w3, h.z, a3.z); a3.w = fmaf(w3, h.w, a3.w);
    }
    float* outp = &g_agg1[(size_t)n * F1];
    float4 acc[4] = { a0, a1, a2, a3 };
    #pragma unroll
    for (int h = 0; h < 4; h++) {
        float4 bb = *(const float4*)&b1[h * HID + lane * 4];
        float4 v = acc[h];
        v.x += bb.x; v.y += bb.y; v.z += bb.z; v.w += bb.w;
        v.x = v.x > 0.f ? v.x : expm1f(v.x);
        v.y = v.y > 0.f ? v.y : expm1f(v.y);
        v.z = v.z > 0.f ? v.z : expm1f(v.z);
        v.w = v.w > 0.f ? v.w : expm1f(v.w);
        *(float4*)&outp[h * HID + lane * 4] = v;
    }
}

// ========= gemm2 tiled + fused logits2: zpre = agg1 @ W2; alS2/alD2 ==========
__global__ __launch_bounds__(256, 2)
void k_gemm2t(const float* __restrict__ W2,
              const float* __restrict__ aS2, const float* __restrict__ aD2) {
    __shared__ unsigned long long As2[BK / 2][BM];
    __shared__ unsigned long long Bs2[BK / 2][32];
    const int tid = threadIdx.x;
    const int tr = tid >> 4;
    const int tc = tid & 15;
    const int rowBase = blockIdx.x * BM;

    unsigned long long acc[8][2];
    #pragma unroll
    for (int i = 0; i < 8; i++) { acc[i][0] = 0ull; acc[i][1] = 0ull; }

    for (int k0 = 0; k0 < F1; k0 += BK) {
        #pragma unroll
        for (int t = 0; t < 2; t++) {
            int i = tid * 2 + t;
            int r = i >> 2;
            int c = (i & 3) * 4;
            int gr = rowBase + r;
            float4 v = make_float4(0.f, 0.f, 0.f, 0.f);
            if (gr < N_NODES) v = *(const float4*)&g_agg1[(size_t)gr * F1 + k0 + c];
            *reinterpret_cast<float2*>(&As2[(c >> 1)][r])     = make_float2(v.x, v.y);
            *reinterpret_cast<float2*>(&As2[(c >> 1) + 1][r]) = make_float2(v.z, v.w);
        }
        {
            #pragma unroll
            for (int t = 0; t < 2; t++) {
                int idx = tid * 2 + t;
                int k = idx >> 5;
                int c = idx & 31;
                float v = (c < OUT_CH) ? W2[(size_t)(k0 + k) * OUT_CH + c] : 0.f;
                float* bs = reinterpret_cast<float*>(&Bs2[k >> 1][0]);
                bs[c * 2 + (k & 1)] = v;
            }
        }
        __syncthreads();
        #pragma unroll
        for (int k2 = 0; k2 < BK / 2; k2++) {
            unsigned long long ap[8], bp[2];
            #pragma unroll
            for (int i2 = 0; i2 < 4; i2++) {
                ulonglong2 a = *reinterpret_cast<const ulonglong2*>(&As2[k2][tr * 8 + i2 * 2]);
                ap[i2 * 2] = a.x; ap[i2 * 2 + 1] = a.y;
            }
            {
                ulonglong2 b = *reinterpret_cast<const ulonglong2*>(&Bs2[k2][tc * 2]);
                bp[0] = b.x; bp[1] = b.y;
            }
            #pragma unroll
            for (int i = 0; i < 8; i++) {
                ffma2(acc[i][0], ap[i], bp[0]);
                ffma2(acc[i][1], ap[i], bp[1]);
            }
        }
        __syncthreads();
    }

    float ps[8], pd[8];
    #pragma unroll
    for (int i = 0; i < 8; i++) { ps[i] = 0.f; pd[i] = 0.f; }
    #pragma unroll
    for (int i = 0; i < 8; i++) {
        int gr = rowBase + tr * 8 + i;
        #pragma unroll
        for (int j = 0; j < 2; j++) {
            int c = tc * 2 + j;
            if (c < OUT_CH) {
                float lo, hi; upk2(acc[i][j], lo, hi);
                float z = lo + hi;
                if (gr < N_NODES) g_zpre[(size_t)gr * OUT_CH + c] = z;
                ps[i] = fmaf(z, aS2[c], ps[i]);
                pd[i] = fmaf(z, aD2[c], pd[i]);
            }
        }
    }
    // reduce over the 16 column-owner lanes (width-16 shfl groups)
    #pragma unroll
    for (int i = 0; i < 8; i++) {
        #pragma unroll
        for (int o = 8; o > 0; o >>= 1) {
            ps[i] += __shfl_down_sync(0xffffffffu, ps[i], o, 16);
            pd[i] += __shfl_down_sync(0xffffffffu, pd[i], o, 16);
        }
    }
    if (tc == 0) {
        #pragma unroll
        for (int i = 0; i < 8; i++) {
            int gr = rowBase + tr * 8 + i;
            if (gr < N_NODES) { g_alS2[gr] = ps[i]; g_alD2[gr] = pd[i]; }
        }
    }
}

// ================= layer 2 fused softmax + aggregate + bias -> outZ =================
__global__ __launch_bounds__(256)
void k_agg2(const float* __restrict__ b2, float* __restrict__ outZ) {
    int warp = (blockIdx.x * blockDim.x + threadIdx.x) >> 5;
    int lane = threadIdx.x & 31;
    if (warp >= N_NODES) return;
    int n = warp;
    int beg = g_rowptr[n], end = g_rowptr[n + 1];
    float ad = g_alD2[n];

    float den = 0.f;
    for (int e = beg + lane; e < end; e += 32) {
        int src = g_csr_src[e];
        float v = g_alS2[src] + ad;
        den += __expf(v > 0.f ? v : NEG_SLOPE * v);
    }
    #pragma unroll
    for (int o = 16; o > 0; o >>= 1) den += __shfl_xor_sync(0xffffffffu, den, o);
    float rden = 1.f / den;

    float acc = 0.f;
    for (int e = beg; e < end; e++) {
        int src = g_csr_src[e];
        float v = g_alS2[src] + ad;
        float alpha = __expf(v > 0.f ? v : NEG_SLOPE * v) * rden;
        if (lane < OUT_CH) acc = fmaf(alpha, g_zpre[src * OUT_CH + lane], acc);
    }
    if (lane < OUT_CH) outZ[n * OUT_CH + lane] = acc + b2[lane];
}

// ================= decoder tiled: out = z[M,30] @ Wd[30,512] + bd =================
#define DBN 64
__global__ __launch_bounds__(256, 2)
void k_decodert(const float* __restrict__ Wd, const float* __restrict__ bd,
                float* __restrict__ out, const float* __restrict__ z) {
    __shared__ float As[32][BM + 4];
    __shared__ float Bs[32][DBN];
    const int tid = threadIdx.x;
    const int tr = tid >> 4;
    const int tc = tid & 15;
    const int rowBase = blockIdx.y * BM;
    const int colBase = blockIdx.x * DBN;

    for (int idx = tid; idx < BM * 32; idx += 256) {
        int r = idx >> 5;
        int k = idx & 31;
        int gr = rowBase + r;
        float v = 0.f;
        if (k < OUT_CH && gr < N_NODES) v = z[(size_t)gr * OUT_CH + k];
        As[k][r] = v;
    }
    for (int idx = tid; idx < 32 * DBN; idx += 256) {
        int k = idx >> 6;
        int c = idx & 63;
        Bs[k][c] = (k < OUT_CH) ? Wd[(size_t)k * IN_CH + colBase + c] : 0.f;
    }
    __syncthreads();

    float acc[8][4];
    {
        float4 bb = *(const float4*)&bd[colBase + tc * 4];
        #pragma unroll
        for (int i = 0; i < 8; i++) {
            acc[i][0] = bb.x; acc[i][1] = bb.y; acc[i][2] = bb.z; acc[i][3] = bb.w;
        }
    }
    #pragma unroll
    for (int k = 0; k < OUT_CH; k++) {
        float a[8], b[4];
        #pragma unroll
        for (int i = 0; i < 8; i += 4)
            *(float4*)&a[i] = *(const float4*)&As[k][tr * 8 + i];
        *(float4*)&b[0] = *(const float4*)&Bs[k][tc * 4];
        #pragma unroll
        for (int i = 0; i < 8; i++)
            #pragma unroll
            for (int j = 0; j < 4; j++) acc[i][j] = fmaf(a[i], b[j], acc[i][j]);
    }
    #pragma unroll
    for (int i = 0; i < 8; i++) {
        int gr = rowBase + tr * 8 + i;
        if (gr >= N_NODES) continue;
        *(float4*)&out[(size_t)gr * IN_CH + colBase + tc * 4] = *(float4*)&acc[i][0];
    }
}

extern "C" void kernel_launch(void* const* d_in, const int* in_sizes, int n_in,
                              void* d_out, int out_size) {
    const float* x   = (const float*)d_in[0];
    const int*   ei  = (const int*)d_in[1];
    const float* W1  = (const float*)d_in[2];
    const float* aS1 = (const float*)d_in[3];
    const float* aD1 = (const float*)d_in[4];
    const float* b1  = (const float*)d_in[5];
    const float* W2  = (const float*)d_in[6];
    const float* aS2 = (const float*)d_in[7];
    const float* aD2 = (const float*)d_in[8];
    const float* b2  = (const float*)d_in[9];
    const float* Wd  = (const float*)d_in[10];
    const float* bd  = (const float*)d_in[11];
    (void)in_sizes; (void)n_in; (void)out_size;

    float* out  = (float*)d_out;
    float* outZ = out + (size_t)N_NODES * IN_CH;

    k_zero_rowptr<<<(N_NODES + 1 + 255) / 256, 256>>>();
    k_count<<<(ET + 255) / 256, 256>>>(ei);
    k_scan<<<1, 1024>>>();
    k_scatter<<<(ET + 255) / 256, 256>>>(ei);

    {
        float* C; cudaGetSymbolAddress((void**)&C, g_h1);
        dim3 grid(F1 / BN, (N_NODES + BM - 1) / BM);
        k_sgemm<<<grid, 256>>>(x, W1, C, N_NODES, F1, IN_CH);
    }

    k_logits1<<<N_NODES, 128>>>(aS1, aD1);
    k_agg1<<<(N_NODES * 32 + 255) / 256, 256>>>(b1);

    k_gemm2t<<<(N_NODES + BM - 1) / BM, 256>>>(W2, aS2, aD2);
    k_agg2<<<(N_NODES * 32 + 255) / 256, 256>>>(b2, outZ);

    {
        dim3 grid(IN_CH / DBN, (N_NODES + BM - 1) / BM);
        k_decodert<<<grid, 256>>>(Wd, bd, out, outZ);
    }
}

// round 8
// speedup vs baseline: 1.6341x; 1.3587x over previous
#include <cuda_runtime.h>
#include <cuda_bf16.h>
#include <cstdint>
#include <float.h>
#include <mma.h>

using namespace nvcuda;

#define N_NODES 20000
#define N_EDGES 320000
#define ET      340000
#define IN_CH   512
#define HID     128
#define HEADS   4
#define F1      512
#define OUT_CH  30
#define NEG_SLOPE 0.2f

#define M_PAD 20096   // N_NODES rounded up to 128

__device__ float g_h1[M_PAD * F1];     // padded for unguarded wmma stores
__device__ float g_agg1[N_NODES * F1];
__device__ float g_alS1[N_NODES * HEADS];
__device__ float g_alD1[N_NODES * HEADS];
__device__ float g_zpre[N_NODES * OUT_CH];
__device__ float g_alS2[N_NODES];
__device__ float g_alD2[N_NODES];
__device__ int   g_rowptr[N_NODES + 1];
__device__ int   g_cursor[N_NODES];
__device__ int   g_csr_src[ET];

__device__ __forceinline__ void edge_endpoints(int e, const int* __restrict__ ei,
                                               int& src, int& dst) {
    if (e < N_EDGES) { src = ei[e]; dst = ei[N_EDGES + e]; }
    else { src = e - N_EDGES; dst = src; }
}

__device__ __forceinline__ void ffma2(unsigned long long& acc,
                                      unsigned long long a, unsigned long long b) {
    asm("fma.rn.f32x2 %0, %1, %2, %0;" : "+l"(acc) : "l"(a), "l"(b));
}
__device__ __forceinline__ void upk2(unsigned long long v, float& lo, float& hi) {
    asm("mov.b64 {%0, %1}, %2;" : "=f"(lo), "=f"(hi) : "l"(v));
}

// ================= CSR build =================
__global__ void k_zero_rowptr() {
    int i = blockIdx.x * blockDim.x + threadIdx.x;
    if (i <= N_NODES) g_rowptr[i] = 0;
}
__global__ void k_count(const int* __restrict__ ei) {
    int e = blockIdx.x * blockDim.x + threadIdx.x;
    if (e >= ET) return;
    int src, dst; edge_endpoints(e, ei, src, dst);
    (void)src;
    atomicAdd(&g_rowptr[dst + 1], 1);
}
__global__ void k_scan() {
    __shared__ int s[1024];
    __shared__ int carry;
    int tid = threadIdx.x;
    if (tid == 0) carry = 0;
    __syncthreads();
    for (int base = 0; base <= N_NODES; base += 1024) {
        int i = base + tid;
        int v = (i <= N_NODES) ? g_rowptr[i] : 0;
        s[tid] = v;
        __syncthreads();
        #pragma unroll
        for (int off = 1; off < 1024; off <<= 1) {
            int t = (tid >= off) ? s[tid - off] : 0;
            __syncthreads();
            s[tid] += t;
            __syncthreads();
        }
        int out = s[tid] + carry;
        if (i <= N_NODES) {
            g_rowptr[i] = out;
            if (i < N_NODES) g_cursor[i] = out;
        }
        __syncthreads();
        if (tid == 1023) carry = out;
        __syncthreads();
    }
}
__global__ void k_scatter(const int* __restrict__ ei) {
    int e = blockIdx.x * blockDim.x + threadIdx.x;
    if (e >= ET) return;
    int src, dst; edge_endpoints(e, ei, src, dst);
    int pos = atomicAdd(&g_cursor[dst], 1);
    g_csr_src[pos] = src;
}

// ========== GEMM1 (tf32 tensor cores): g_h1 = x[M,512] @ W1[512,512] ==========
// block tile 128x64, 8 warps in 4x2, warp tile 32x32 = 2x2 wmma m16n16k8
#define BM 128
#define BN 64
#define BK 16
#define LDA (BK + 4)
#define LDB (BN + 4)
__global__ __launch_bounds__(256, 2)
void k_gemm_tf32(const float* __restrict__ A, const float* __restrict__ B) {
    __shared__ float As[BM][LDA];
    __shared__ float Bs[BK][LDB];
    const int tid = threadIdx.x;
    const int wid = tid >> 5;
    const int wm = wid >> 1;      // 0..3
    const int wn = wid & 1;       // 0..1
    const int rowBase = blockIdx.y * BM;
    const int colBase = blockIdx.x * BN;

    wmma::fragment<wmma::accumulator, 16, 16, 8, float> acc[2][2];
    #pragma unroll
    for (int i = 0; i < 2; i++)
        #pragma unroll
        for (int j = 0; j < 2; j++) wmma::fill_fragment(acc[i][j], 0.f);

    for (int k0 = 0; k0 < IN_CH; k0 += BK) {
        // A tile 128x16
        #pragma unroll
        for (int t = 0; t < 2; t++) {
            int idx = tid * 2 + t;
            int r = idx >> 2;
            int c = (idx & 3) * 4;
            int gr = rowBase + r;
            float4 v = make_float4(0.f, 0.f, 0.f, 0.f);
            if (gr < N_NODES) v = *(const float4*)&A[(size_t)gr * IN_CH + k0 + c];
            As[r][c + 0] = wmma::__float_to_tf32(v.x);
            As[r][c + 1] = wmma::__float_to_tf32(v.y);
            As[r][c + 2] = wmma::__float_to_tf32(v.z);
            As[r][c + 3] = wmma::__float_to_tf32(v.w);
        }
        // B tile 16x64
        {
            int r = tid >> 4;
            int c = (tid & 15) * 4;
            float4 v = *(const float4*)&B[(size_t)(k0 + r) * F1 + colBase + c];
            Bs[r][c + 0] = wmma::__float_to_tf32(v.x);
            Bs[r][c + 1] = wmma::__float_to_tf32(v.y);
            Bs[r][c + 2] = wmma::__float_to_tf32(v.z);
            Bs[r][c + 3] = wmma::__float_to_tf32(v.w);
        }
        __syncthreads();
        #pragma unroll
        for (int kk = 0; kk < BK; kk += 8) {
            wmma::fragment<wmma::matrix_a, 16, 16, 8, wmma::precision::tf32, wmma::row_major> fa[2];
            wmma::fragment<wmma::matrix_b, 16, 16, 8, wmma::precision::tf32, wmma::row_major> fb[2];
            #pragma unroll
            for (int i = 0; i < 2; i++)
                wmma::load_matrix_sync(fa[i], &As[wm * 32 + i * 16][kk], LDA);
            #pragma unroll
            for (int j = 0; j < 2; j++)
                wmma::load_matrix_sync(fb[j], &Bs[kk][wn * 32 + j * 16], LDB);
            #pragma unroll
            for (int i = 0; i < 2; i++)
                #pragma unroll
                for (int j = 0; j < 2; j++)
                    wmma::mma_sync(acc[i][j], fa[i], fb[j], acc[i][j]);
        }
        __syncthreads();
    }
    #pragma unroll
    for (int i = 0; i < 2; i++)
        #pragma unroll
        for (int j = 0; j < 2; j++) {
            int r = rowBase + wm * 32 + i * 16;     // < M_PAD always (g_h1 padded)
            int c = colBase + wn * 32 + j * 16;
            wmma::store_matrix_sync(&g_h1[(size_t)r * F1 + c], acc[i][j], F1,
                                    wmma::mem_row_major);
        }
}

// ================= layer 1 attention logits per node =================
__global__ void k_logits1(const float* __restrict__ aS, const float* __restrict__ aD) {
    int n = blockIdx.x;
    int w = threadIdx.x >> 5, lane = threadIdx.x & 31;
    const float* hr = g_h1 + (size_t)n * F1 + w * HID;
    const float* av = aS + w * HID;
    const float* dv = aD + w * HID;
    float s = 0.f, d = 0.f;
    #pragma unroll
    for (int i = 0; i < 4; i++) {
        float hv = hr[lane + i * 32];
        s = fmaf(hv, av[lane + i * 32], s);
        d = fmaf(hv, dv[lane + i * 32], d);
    }
    #pragma unroll
    for (int o = 16; o > 0; o >>= 1) {
        s += __shfl_down_sync(0xffffffffu, s, o);
        d += __shfl_down_sync(0xffffffffu, d, o);
    }
    if (lane == 0) { g_alS1[n * HEADS + w] = s; g_alD1[n * HEADS + w] = d; }
}

// ================= layer 1 fused softmax + aggregate + bias + ELU =================
__global__ __launch_bounds__(256)
void k_agg1(const float* __restrict__ b1) {
    int warp = (blockIdx.x * blockDim.x + threadIdx.x) >> 5;
    int lane = threadIdx.x & 31;
    if (warp >= N_NODES) return;
    int n = warp;
    int beg = g_rowptr[n], end = g_rowptr[n + 1];
    float4 ad = *(const float4*)&g_alD1[n * 4];

    float4 den = make_float4(0.f, 0.f, 0.f, 0.f);
    for (int e = beg + lane; e < end; e += 32) {
        int src = g_csr_src[e];
        float4 s = *(const float4*)&g_alS1[src * 4];
        float v;
        v = s.x + ad.x; den.x += __expf(v > 0.f ? v : NEG_SLOPE * v);
        v = s.y + ad.y; den.y += __expf(v > 0.f ? v : NEG_SLOPE * v);
        v = s.z + ad.z; den.z += __expf(v > 0.f ? v : NEG_SLOPE * v);
        v = s.w + ad.w; den.w += __expf(v > 0.f ? v : NEG_SLOPE * v);
    }
    #pragma unroll
    for (int o = 16; o > 0; o >>= 1) {
        den.x += __shfl_xor_sync(0xffffffffu, den.x, o);
        den.y += __shfl_xor_sync(0xffffffffu, den.y, o);
        den.z += __shfl_xor_sync(0xffffffffu, den.z, o);
        den.w += __shfl_xor_sync(0xffffffffu, den.w, o);
    }
    float r0 = 1.f / den.x, r1 = 1.f / den.y, r2 = 1.f / den.z, r3 = 1.f / den.w;

    float4 a0 = make_float4(0.f, 0.f, 0.f, 0.f);
    float4 a1 = a0, a2 = a0, a3 = a0;
    for (int e = beg; e < end; e++) {
        int src = g_csr_src[e];
        float4 s = *(const float4*)&g_alS1[src * 4];
        float v, w0, w1, w2, w3;
        v = s.x + ad.x; w0 = __expf(v > 0.f ? v : NEG_SLOPE * v) * r0;
        v = s.y + ad.y; w1 = __expf(v > 0.f ? v : NEG_SLOPE * v) * r1;
        v = s.z + ad.z; w2 = __expf(v > 0.f ? v : NEG_SLOPE * v) * r2;
        v = s.w + ad.w; w3 = __expf(v > 0.f ? v : NEG_SLOPE * v) * r3;
        const float4* hp = (const float4*)&g_h1[(size_t)src * F1];
        float4 h;
        h = hp[lane];      a0.x = fmaf(w0, h.x, a0.x); a0.y = fmaf(w0, h.y, a0.y); a0.z = fmaf(w0, h.z, a0.z); a0.w = fmaf(w0, h.w, a0.w);
        h = hp[32 + lane]; a1.x = fmaf(w1, h.x, a1.x); a1.y = fmaf(w1, h.y, a1.y); a1.z = fmaf(w1, h.z, a1.z); a1.w = fmaf(w1, h.w, a1.w);
        h = hp[64 + lane]; a2.x = fmaf(w2, h.x, a2.x); a2.y = fmaf(w2, h.y, a2.y); a2.z = fmaf(w2, h.z, a2.z); a2.w = fmaf(w2, h.w, a2.w);
        h = hp[96 + lane]; a3.x = fmaf(w3, h.x, a3.x); a3.y = fmaf(w3, h.y, a3.y); a3.z = fmaf(w3, h.z, a3.z); a3.w = fmaf(w3, h.w, a3.w);
    }
    float* outp = &g_agg1[(size_t)n * F1];
    float4 acc[4] = { a0, a1, a2, a3 };
    #pragma unroll
    for (int h = 0; h < 4; h++) {
        float4 bb = *(const float4*)&b1[h * HID + lane * 4];
        float4 v = acc[h];
        v.x += bb.x; v.y += bb.y; v.z += bb.z; v.w += bb.w;
        v.x = v.x > 0.f ? v.x : expm1f(v.x);
        v.y = v.y > 0.f ? v.y : expm1f(v.y);
        v.z = v.z > 0.f ? v.z : expm1f(v.z);
        v.w = v.w > 0.f ? v.w : expm1f(v.w);
        *(float4*)&outp[h * HID + lane * 4] = v;
    }
}

// ========= gemm2 tiled + fused logits2: zpre = agg1 @ W2; alS2/alD2 ==========
__global__ __launch_bounds__(256, 2)
void k_gemm2t(const float* __restrict__ W2,
              const float* __restrict__ aS2, const float* __restrict__ aD2) {
    __shared__ unsigned long long As2[BK / 2][BM];
    __shared__ unsigned long long Bs2[BK / 2][32];
    const int tid = threadIdx.x;
    const int tr = tid >> 4;
    const int tc = tid & 15;
    const int rowBase = blockIdx.x * BM;

    unsigned long long acc[8][2];
    #pragma unroll
    for (int i = 0; i < 8; i++) { acc[i][0] = 0ull; acc[i][1] = 0ull; }

    for (int k0 = 0; k0 < F1; k0 += BK) {
        #pragma unroll
        for (int t = 0; t < 2; t++) {
            int i = tid * 2 + t;
            int r = i >> 2;
            int c = (i & 3) * 4;
            int gr = rowBase + r;
            float4 v = make_float4(0.f, 0.f, 0.f, 0.f);
            if (gr < N_NODES) v = *(const float4*)&g_agg1[(size_t)gr * F1 + k0 + c];
            *reinterpret_cast<float2*>(&As2[(c >> 1)][r])     = make_float2(v.x, v.y);
            *reinterpret_cast<float2*>(&As2[(c >> 1) + 1][r]) = make_float2(v.z, v.w);
        }
        {
            #pragma unroll
            for (int t = 0; t < 2; t++) {
                int idx = tid * 2 + t;
                int k = idx >> 5;
                int c = idx & 31;
                float v = (c < OUT_CH) ? W2[(size_t)(k0 + k) * OUT_CH + c] : 0.f;
                float* bs = reinterpret_cast<float*>(&Bs2[k >> 1][0]);
                bs[c * 2 + (k & 1)] = v;
            }
        }
        __syncthreads();
        #pragma unroll
        for (int k2 = 0; k2 < BK / 2; k2++) {
            unsigned long long ap[8], bp[2];
            #pragma unroll
            for (int i2 = 0; i2 < 4; i2++) {
                ulonglong2 a = *reinterpret_cast<const ulonglong2*>(&As2[k2][tr * 8 + i2 * 2]);
                ap[i2 * 2] = a.x; ap[i2 * 2 + 1] = a.y;
            }
            {
                ulonglong2 b = *reinterpret_cast<const ulonglong2*>(&Bs2[k2][tc * 2]);
                bp[0] = b.x; bp[1] = b.y;
            }
            #pragma unroll
            for (int i = 0; i < 8; i++) {
                ffma2(acc[i][0], ap[i], bp[0]);
                ffma2(acc[i][1], ap[i], bp[1]);
            }
        }
        __syncthreads();
    }

    float ps[8], pd[8];
    #pragma unroll
    for (int i = 0; i < 8; i++) { ps[i] = 0.f; pd[i] = 0.f; }
    #pragma unroll
    for (int i = 0; i < 8; i++) {
        int gr = rowBase + tr * 8 + i;
        #pragma unroll
        for (int j = 0; j < 2; j++) {
            int c = tc * 2 + j;
            if (c < OUT_CH) {
                float lo, hi; upk2(acc[i][j], lo, hi);
                float z = lo + hi;
                if (gr < N_NODES) g_zpre[(size_t)gr * OUT_CH + c] = z;
                ps[i] = fmaf(z, aS2[c], ps[i]);
                pd[i] = fmaf(z, aD2[c], pd[i]);
            }
        }
    }
    #pragma unroll
    for (int i = 0; i < 8; i++) {
        #pragma unroll
        for (int o = 8; o > 0; o >>= 1) {
            ps[i] += __shfl_down_sync(0xffffffffu, ps[i], o, 16);
            pd[i] += __shfl_down_sync(0xffffffffu, pd[i], o, 16);
        }
    }
    if (tc == 0) {
        #pragma unroll
        for (int i = 0; i < 8; i++) {
            int gr = rowBase + tr * 8 + i;
            if (gr < N_NODES) { g_alS2[gr] = ps[i]; g_alD2[gr] = pd[i]; }
        }
    }
}

// ================= layer 2 fused softmax + aggregate + bias -> outZ =================
__global__ __launch_bounds__(256)
void k_agg2(const float* __restrict__ b2, float* __restrict__ outZ) {
    int warp = (blockIdx.x * blockDim.x + threadIdx.x) >> 5;
    int lane = threadIdx.x & 31;
    if (warp >= N_NODES) return;
    int n = warp;
    int beg = g_rowptr[n], end = g_rowptr[n + 1];
    float ad = g_alD2[n];

    float den = 0.f;
    for (int e = beg + lane; e < end; e += 32) {
        int src = g_csr_src[e];
        float v = g_alS2[src] + ad;
        den += __expf(v > 0.f ? v : NEG_SLOPE * v);
    }
    #pragma unroll
    for (int o = 16; o > 0; o >>= 1) den += __shfl_xor_sync(0xffffffffu, den, o);
    float rden = 1.f / den;

    float acc = 0.f;
    for (int e = beg; e < end; e++) {
        int src = g_csr_src[e];
        float v = g_alS2[src] + ad;
        float alpha = __expf(v > 0.f ? v : NEG_SLOPE * v) * rden;
        if (lane < OUT_CH) acc = fmaf(alpha, g_zpre[src * OUT_CH + lane], acc);
    }
    if (lane < OUT_CH) outZ[n * OUT_CH + lane] = acc + b2[lane];
}

// ================= decoder tiled: out = z[M,30] @ Wd[30,512] + bd =================
#define DBN 64
__global__ __launch_bounds__(256, 2)
void k_decodert(const float* __restrict__ Wd, const float* __restrict__ bd,
                float* __restrict__ out, const float* __restrict__ z) {
    __shared__ float As[32][BM + 4];
    __shared__ float Bs[32][DBN];
    const int tid = threadIdx.x;
    const int tr = tid >> 4;
    const int tc = tid & 15;
    const int rowBase = blockIdx.y * BM;
    const int colBase = blockIdx.x * DBN;

    for (int idx = tid; idx < BM * 32; idx += 256) {
        int r = idx >> 5;
        int k = idx & 31;
        int gr = rowBase + r;
        float v = 0.f;
        if (k < OUT_CH && gr < N_NODES) v = z[(size_t)gr * OUT_CH + k];
        As[k][r] = v;
    }
    for (int idx = tid; idx < 32 * DBN; idx += 256) {
        int k = idx >> 6;
        int c = idx & 63;
        Bs[k][c] = (k < OUT_CH) ? Wd[(size_t)k * IN_CH + colBase + c] : 0.f;
    }
    __syncthreads();

    float acc[8][4];
    {
        float4 bb = *(const float4*)&bd[colBase + tc * 4];
        #pragma unroll
        for (int i = 0; i < 8; i++) {
            acc[i][0] = bb.x; acc[i][1] = bb.y; acc[i][2] = bb.z; acc[i][3] = bb.w;
        }
    }
    #pragma unroll
    for (int k = 0; k < OUT_CH; k++) {
        float a[8], b[4];
        #pragma unroll
        for (int i = 0; i < 8; i += 4)
            *(float4*)&a[i] = *(const float4*)&As[k][tr * 8 + i];
        *(float4*)&b[0] = *(const float4*)&Bs[k][tc * 4];
        #pragma unroll
        for (int i = 0; i < 8; i++)
            #pragma unroll
            for (int j = 0; j < 4; j++) acc[i][j] = fmaf(a[i], b[j], acc[i][j]);
    }
    #pragma unroll
    for (int i = 0; i < 8; i++) {
        int gr = rowBase + tr * 8 + i;
        if (gr >= N_NODES) continue;
        *(float4*)&out[(size_t)gr * IN_CH + colBase + tc * 4] = *(float4*)&acc[i][0];
    }
}

extern "C" void kernel_launch(void* const* d_in, const int* in_sizes, int n_in,
                              void* d_out, int out_size) {
    const float* x   = (const float*)d_in[0];
    const int*   ei  = (const int*)d_in[1];
    const float* W1  = (const float*)d_in[2];
    const float* aS1 = (const float*)d_in[3];
    const float* aD1 = (const float*)d_in[4];
    const float* b1  = (const float*)d_in[5];
    const float* W2  = (const float*)d_in[6];
    const float* aS2 = (const float*)d_in[7];
    const float* aD2 = (const float*)d_in[8];
    const float* b2  = (const float*)d_in[9];
    const float* Wd  = (const float*)d_in[10];
    const float* bd  = (const float*)d_in[11];
    (void)in_sizes; (void)n_in; (void)out_size;

    float* out  = (float*)d_out;
    float* outZ = out + (size_t)N_NODES * IN_CH;

    k_zero_rowptr<<<(N_NODES + 1 + 255) / 256, 256>>>();
    k_count<<<(ET + 255) / 256, 256>>>(ei);
    k_scan<<<1, 1024>>>();
    k_scatter<<<(ET + 255) / 256, 256>>>(ei);

    {
        dim3 grid(F1 / BN, M_PAD / BM);
        k_gemm_tf32<<<grid, 256>>>(x, W1);
    }

    k_logits1<<<N_NODES, 128>>>(aS1, aD1);
    k_agg1<<<(N_NODES * 32 + 255) / 256, 256>>>(b1);

    k_gemm2t<<<(N_NODES + BM - 1) / BM, 256>>>(W2, aS2, aD2);
    k_agg2<<<(N_NODES * 32 + 255) / 256, 256>>>(b2, outZ);

    {
        dim3 grid(IN_CH / DBN, (N_NODES + BM - 1) / BM);
        k_decodert<<<grid, 256>>>(Wd, bd, out, outZ);
    }
}

// round 9
// speedup vs baseline: 1.6527x; 1.0113x over previous
#include <cuda_runtime.h>
#include <cuda_bf16.h>
#include <cstdint>
#include <float.h>
#include <mma.h>

using namespace nvcuda;

#define N_NODES 20000
#define N_EDGES 320000
#define ET      340000
#define IN_CH   512
#define HID     128
#define HEADS   4
#define F1      512
#define OUT_CH  30
#define NEG_SLOPE 0.2f

#define M_PAD 20096   // N_NODES rounded up to 128
#define ZP    32      // padded z width

__device__ float g_h1[M_PAD * F1];       // padded for unguarded wmma stores
__device__ float g_agg1[N_NODES * F1];
__device__ float g_alS1[N_NODES * HEADS];
__device__ float g_alD1[N_NODES * HEADS];
__device__ float g_zpre32[M_PAD * ZP];   // padded z_pre
__device__ float g_alS2[N_NODES];
__device__ float g_alD2[N_NODES];
__device__ int   g_rowptr[N_NODES + 1];
__device__ int   g_cursor[N_NODES];
__device__ int   g_csr_src[ET];

__device__ __forceinline__ void edge_endpoints(int e, const int* __restrict__ ei,
                                               int& src, int& dst) {
    if (e < N_EDGES) { src = ei[e]; dst = ei[N_EDGES + e]; }
    else { src = e - N_EDGES; dst = src; }
}

// ================= CSR build =================
__global__ void k_zero_rowptr() {
    int i = blockIdx.x * blockDim.x + threadIdx.x;
    if (i <= N_NODES) g_rowptr[i] = 0;
}
__global__ void k_count(const int* __restrict__ ei) {
    int e = blockIdx.x * blockDim.x + threadIdx.x;
    if (e >= ET) return;
    int src, dst; edge_endpoints(e, ei, src, dst);
    (void)src;
    atomicAdd(&g_rowptr[dst + 1], 1);
}
__global__ void k_scan() {
    __shared__ int s[1024];
    __shared__ int carry;
    int tid = threadIdx.x;
    if (tid == 0) carry = 0;
    __syncthreads();
    for (int base = 0; base <= N_NODES; base += 1024) {
        int i = base + tid;
        int v = (i <= N_NODES) ? g_rowptr[i] : 0;
        s[tid] = v;
        __syncthreads();
        #pragma unroll
        for (int off = 1; off < 1024; off <<= 1) {
            int t = (tid >= off) ? s[tid - off] : 0;
            __syncthreads();
            s[tid] += t;
            __syncthreads();
        }
        int out = s[tid] + carry;
        if (i <= N_NODES) {
            g_rowptr[i] = out;
            if (i < N_NODES) g_cursor[i] = out;
        }
        __syncthreads();
        if (tid == 1023) carry = out;
        __syncthreads();
    }
}
__global__ void k_scatter(const int* __restrict__ ei) {
    int e = blockIdx.x * blockDim.x + threadIdx.x;
    if (e >= ET) return;
    int src, dst; edge_endpoints(e, ei, src, dst);
    int pos = atomicAdd(&g_cursor[dst], 1);
    g_csr_src[pos] = src;
}

// ========== GEMM1 (tf32): g_h1 = x[M,512] @ W1[512,512] ==========
#define BM 128
#define BN 64
#define BK 16
#define LDA (BK + 4)
#define LDB (BN + 4)
__global__ __launch_bounds__(256, 2)
void k_gemm_tf32(const float* __restrict__ A, const float* __restrict__ B) {
    __shared__ float As[BM][LDA];
    __shared__ float Bs[BK][LDB];
    const int tid = threadIdx.x;
    const int wid = tid >> 5;
    const int wm = wid >> 1;
    const int wn = wid & 1;
    const int rowBase = blockIdx.y * BM;
    const int colBase = blockIdx.x * BN;

    wmma::fragment<wmma::accumulator, 16, 16, 8, float> acc[2][2];
    #pragma unroll
    for (int i = 0; i < 2; i++)
        #pragma unroll
        for (int j = 0; j < 2; j++) wmma::fill_fragment(acc[i][j], 0.f);

    for (int k0 = 0; k0 < IN_CH; k0 += BK) {
        #pragma unroll
        for (int t = 0; t < 2; t++) {
            int idx = tid * 2 + t;
            int r = idx >> 2;
            int c = (idx & 3) * 4;
            int gr = rowBase + r;
            float4 v = make_float4(0.f, 0.f, 0.f, 0.f);
            if (gr < N_NODES) v = *(const float4*)&A[(size_t)gr * IN_CH + k0 + c];
            As[r][c + 0] = wmma::__float_to_tf32(v.x);
            As[r][c + 1] = wmma::__float_to_tf32(v.y);
            As[r][c + 2] = wmma::__float_to_tf32(v.z);
            As[r][c + 3] = wmma::__float_to_tf32(v.w);
        }
        {
            int r = tid >> 4;
            int c = (tid & 15) * 4;
            float4 v = *(const float4*)&B[(size_t)(k0 + r) * F1 + colBase + c];
            Bs[r][c + 0] = wmma::__float_to_tf32(v.x);
            Bs[r][c + 1] = wmma::__float_to_tf32(v.y);
            Bs[r][c + 2] = wmma::__float_to_tf32(v.z);
            Bs[r][c + 3] = wmma::__float_to_tf32(v.w);
        }
        __syncthreads();
        #pragma unroll
        for (int kk = 0; kk < BK; kk += 8) {
            wmma::fragment<wmma::matrix_a, 16, 16, 8, wmma::precision::tf32, wmma::row_major> fa[2];
            wmma::fragment<wmma::matrix_b, 16, 16, 8, wmma::precision::tf32, wmma::row_major> fb[2];
            #pragma unroll
            for (int i = 0; i < 2; i++)
                wmma::load_matrix_sync(fa[i], &As[wm * 32 + i * 16][kk], LDA);
            #pragma unroll
            for (int j = 0; j < 2; j++)
                wmma::load_matrix_sync(fb[j], &Bs[kk][wn * 32 + j * 16], LDB);
            #pragma unroll
            for (int i = 0; i < 2; i++)
                #pragma unroll
                for (int j = 0; j < 2; j++)
                    wmma::mma_sync(acc[i][j], fa[i], fb[j], acc[i][j]);
        }
        __syncthreads();
    }
    #pragma unroll
    for (int i = 0; i < 2; i++)
        #pragma unroll
        for (int j = 0; j < 2; j++) {
            int r = rowBase + wm * 32 + i * 16;
            int c = colBase + wn * 32 + j * 16;
            wmma::store_matrix_sync(&g_h1[(size_t)r * F1 + c], acc[i][j], F1,
                                    wmma::mem_row_major);
        }
}

// ========== GEMM2 (tf32): g_zpre32 = agg1[M,512] @ W2pad[512,32] ==========
#define BN2 32
#define LDB2 (BN2 + 4)
__global__ __launch_bounds__(256, 2)
void k_gemm2_tf32(const float* __restrict__ W2) {
    __shared__ float As[BM][LDA];
    __shared__ float Bs[BK][LDB2];
    const int tid = threadIdx.x;
    const int wid = tid >> 5;
    const int wm = wid >> 1;      // 0..3 (m group of 32 rows)
    const int wn = wid & 1;       // 0..1 (n group of 16 cols)
    const int rowBase = blockIdx.x * BM;

    wmma::fragment<wmma::accumulator, 16, 16, 8, float> acc[2];
    wmma::fill_fragment(acc[0], 0.f);
    wmma::fill_fragment(acc[1], 0.f);

    for (int k0 = 0; k0 < F1; k0 += BK) {
        #pragma unroll
        for (int t = 0; t < 2; t++) {
            int idx = tid * 2 + t;
            int r = idx >> 2;
            int c = (idx & 3) * 4;
            int gr = rowBase + r;
            float4 v = make_float4(0.f, 0.f, 0.f, 0.f);
            if (gr < N_NODES) v = *(const float4*)&g_agg1[(size_t)gr * F1 + k0 + c];
            As[r][c + 0] = wmma::__float_to_tf32(v.x);
            As[r][c + 1] = wmma::__float_to_tf32(v.y);
            As[r][c + 2] = wmma::__float_to_tf32(v.z);
            As[r][c + 3] = wmma::__float_to_tf32(v.w);
        }
        {   // B tile 16x32, W2 has 30 real cols; 512 elems, 2/thread
            #pragma unroll
            for (int t = 0; t < 2; t++) {
                int idx = tid * 2 + t;
                int r = idx >> 5;         // 0..15
                int c = idx & 31;         // 0..31
                float v = (c < OUT_CH) ? W2[(size_t)(k0 + r) * OUT_CH + c] : 0.f;
                Bs[r][c] = wmma::__float_to_tf32(v);
            }
        }
        __syncthreads();
        #pragma unroll
        for (int kk = 0; kk < BK; kk += 8) {
            wmma::fragment<wmma::matrix_a, 16, 16, 8, wmma::precision::tf32, wmma::row_major> fa[2];
            wmma::fragment<wmma::matrix_b, 16, 16, 8, wmma::precision::tf32, wmma::row_major> fb;
            #pragma unroll
            for (int i = 0; i < 2; i++)
                wmma::load_matrix_sync(fa[i], &As[wm * 32 + i * 16][kk], LDA);
            wmma::load_matrix_sync(fb, &Bs[kk][wn * 16], LDB2);
            #pragma unroll
            for (int i = 0; i < 2; i++)
                wmma::mma_sync(acc[i], fa[i], fb, acc[i]);
        }
        __syncthreads();
    }
    #pragma unroll
    for (int i = 0; i < 2; i++) {
        int r = rowBase + wm * 32 + i * 16;   // < M_PAD always
        int c = wn * 16;
        wmma::store_matrix_sync(&g_zpre32[(size_t)r * ZP + c], acc[i], ZP,
                                wmma::mem_row_major);
    }
}

// ================= logits2: warp per node =================
__global__ __launch_bounds__(256)
void k_logits2(const float* __restrict__ aS2, const float* __restrict__ aD2) {
    int warp = (blockIdx.x * blockDim.x + threadIdx.x) >> 5;
    int lane = threadIdx.x & 31;
    if (warp >= N_NODES) return;
    float z = (lane < OUT_CH) ? g_zpre32[(size_t)warp * ZP + lane] : 0.f;
    float ps = (lane < OUT_CH) ? z * aS2[lane] : 0.f;
    float pd = (lane < OUT_CH) ? z * aD2[lane] : 0.f;
    #pragma unroll
    for (int o = 16; o > 0; o >>= 1) {
        ps += __shfl_down_sync(0xffffffffu, ps, o);
        pd += __shfl_down_sync(0xffffffffu, pd, o);
    }
    if (lane == 0) { g_alS2[warp] = ps; g_alD2[warp] = pd; }
}

// ================= layer 1 attention logits per node =================
__global__ void k_logits1(const float* __restrict__ aS, const float* __restrict__ aD) {
    int n = blockIdx.x;
    int w = threadIdx.x >> 5, lane = threadIdx.x & 31;
    const float* hr = g_h1 + (size_t)n * F1 + w * HID;
    const float* av = aS + w * HID;
    const float* dv = aD + w * HID;
    float s = 0.f, d = 0.f;
    #pragma unroll
    for (int i = 0; i < 4; i++) {
        float hv = hr[lane + i * 32];
        s = fmaf(hv, av[lane + i * 32], s);
        d = fmaf(hv, dv[lane + i * 32], d);
    }
    #pragma unroll
    for (int o = 16; o > 0; o >>= 1) {
        s += __shfl_down_sync(0xffffffffu, s, o);
        d += __shfl_down_sync(0xffffffffu, d, o);
    }
    if (lane == 0) { g_alS1[n * HEADS + w] = s; g_alD1[n * HEADS + w] = d; }
}

// ================= layer 1 fused softmax + aggregate + bias + ELU =================
__global__ __launch_bounds__(256)
void k_agg1(const float* __restrict__ b1) {
    int warp = (blockIdx.x * blockDim.x + threadIdx.x) >> 5;
    int lane = threadIdx.x & 31;
    if (warp >= N_NODES) return;
    int n = warp;
    int beg = g_rowptr[n], end = g_rowptr[n + 1];
    float4 ad = *(const float4*)&g_alD1[n * 4];

    float4 den = make_float4(0.f, 0.f, 0.f, 0.f);
    for (int e = beg + lane; e < end; e += 32) {
        int src = g_csr_src[e];
        float4 s = *(const float4*)&g_alS1[src * 4];
        float v;
        v = s.x + ad.x; den.x += __expf(v > 0.f ? v : NEG_SLOPE * v);
        v = s.y + ad.y; den.y += __expf(v > 0.f ? v : NEG_SLOPE * v);
        v = s.z + ad.z; den.z += __expf(v > 0.f ? v : NEG_SLOPE * v);
        v = s.w + ad.w; den.w += __expf(v > 0.f ? v : NEG_SLOPE * v);
    }
    #pragma unroll
    for (int o = 16; o > 0; o >>= 1) {
        den.x += __shfl_xor_sync(0xffffffffu, den.x, o);
        den.y += __shfl_xor_sync(0xffffffffu, den.y, o);
        den.z += __shfl_xor_sync(0xffffffffu, den.z, o);
        den.w += __shfl_xor_sync(0xffffffffu, den.w, o);
    }
    float r0 = 1.f / den.x, r1 = 1.f / den.y, r2 = 1.f / den.z, r3 = 1.f / den.w;

    float4 a0 = make_float4(0.f, 0.f, 0.f, 0.f);
    float4 a1 = a0, a2 = a0, a3 = a0;
    for (int e = beg; e < end; e++) {
        int src = g_csr_src[e];
        float4 s = *(const float4*)&g_alS1[src * 4];
        float v, w0, w1, w2, w3;
        v = s.x + ad.x; w0 = __expf(v > 0.f ? v : NEG_SLOPE * v) * r0;
        v = s.y + ad.y; w1 = __expf(v > 0.f ? v : NEG_SLOPE * v) * r1;
        v = s.z + ad.z; w2 = __expf(v > 0.f ? v : NEG_SLOPE * v) * r2;
        v = s.w + ad.w; w3 = __expf(v > 0.f ? v : NEG_SLOPE * v) * r3;
        const float4* hp = (const float4*)&g_h1[(size_t)src * F1];
        float4 h;
        h = hp[lane];      a0.x = fmaf(w0, h.x, a0.x); a0.y = fmaf(w0, h.y, a0.y); a0.z = fmaf(w0, h.z, a0.z); a0.w = fmaf(w0, h.w, a0.w);
        h = hp[32 + lane]; a1.x = fmaf(w1, h.x, a1.x); a1.y = fmaf(w1, h.y, a1.y); a1.z = fmaf(w1, h.z, a1.z); a1.w = fmaf(w1, h.w, a1.w);
        h = hp[64 + lane]; a2.x = fmaf(w2, h.x, a2.x); a2.y = fmaf(w2, h.y, a2.y); a2.z = fmaf(w2, h.z, a2.z); a2.w = fmaf(w2, h.w, a2.w);
        h = hp[96 + lane]; a3.x = fmaf(w3, h.x, a3.x); a3.y = fmaf(w3, h.y, a3.y); a3.z = fmaf(w3, h.z, a3.z); a3.w = fmaf(w3, h.w, a3.w);
    }
    float* outp = &g_agg1[(size_t)n * F1];
    float4 acc[4] = { a0, a1, a2, a3 };
    #pragma unroll
    for (int h = 0; h < 4; h++) {
        float4 bb = *(const float4*)&b1[h * HID + lane * 4];
        float4 v = acc[h];
        v.x += bb.x; v.y += bb.y; v.z += bb.z; v.w += bb.w;
        v.x = v.x > 0.f ? v.x : expm1f(v.x);
        v.y = v.y > 0.f ? v.y : expm1f(v.y);
        v.z = v.z > 0.f ? v.z : expm1f(v.z);
        v.w = v.w > 0.f ? v.w : expm1f(v.w);
        *(float4*)&outp[h * HID + lane * 4] = v;
    }
}

// ================= layer 2 fused softmax + aggregate + bias -> outZ =================
__global__ __launch_bounds__(256)
void k_agg2(const float* __restrict__ b2, float* __restrict__ outZ) {
    int warp = (blockIdx.x * blockDim.x + threadIdx.x) >> 5;
    int lane = threadIdx.x & 31;
    if (warp >= N_NODES) return;
    int n = warp;
    int beg = g_rowptr[n], end = g_rowptr[n + 1];
    float ad = g_alD2[n];

    float den = 0.f;
    for (int e = beg + lane; e < end; e += 32) {
        int src = g_csr_src[e];
        float v = g_alS2[src] + ad;
        den += __expf(v > 0.f ? v : NEG_SLOPE * v);
    }
    #pragma unroll
    for (int o = 16; o > 0; o >>= 1) den += __shfl_xor_sync(0xffffffffu, den, o);
    float rden = 1.f / den;

    float acc = 0.f;
    for (int e = beg; e < end; e++) {
        int src = g_csr_src[e];
        float v = g_alS2[src] + ad;
        float alpha = __expf(v > 0.f ? v : NEG_SLOPE * v) * rden;
        if (lane < OUT_CH) acc = fmaf(alpha, g_zpre32[(size_t)src * ZP + lane], acc);
    }
    if (lane < OUT_CH) outZ[n * OUT_CH + lane] = acc + b2[lane];
}

// ================= decoder tiled: out = z[M,30] @ Wd[30,512] + bd =================
#define DBN 64
__global__ __launch_bounds__(256, 2)
void k_decodert(const float* __restrict__ Wd, const float* __restrict__ bd,
                float* __restrict__ out, const float* __restrict__ z) {
    __shared__ float As[32][BM + 4];
    __shared__ float Bs[32][DBN];
    const int tid = threadIdx.x;
    const int tr = tid >> 4;
    const int tc = tid & 15;
    const int rowBase = blockIdx.y * BM;
    const int colBase = blockIdx.x * DBN;

    for (int idx = tid; idx < BM * 32; idx += 256) {
        int r = idx >> 5;
        int k = idx & 31;
        int gr = rowBase + r;
        float v = 0.f;
        if (k < OUT_CH && gr < N_NODES) v = z[(size_t)gr * OUT_CH + k];
        As[k][r] = v;
    }
    for (int idx = tid; idx < 32 * DBN; idx += 256) {
        int k = idx >> 6;
        int c = idx & 63;
        Bs[k][c] = (k < OUT_CH) ? Wd[(size_t)k * IN_CH + colBase + c] : 0.f;
    }
    __syncthreads();

    float acc[8][4];
    {
        float4 bb = *(const float4*)&bd[colBase + tc * 4];
        #pragma unroll
        for (int i = 0; i < 8; i++) {
            acc[i][0] = bb.x; acc[i][1] = bb.y; acc[i][2] = bb.z; acc[i][3] = bb.w;
        }
    }
    #pragma unroll
    for (int k = 0; k < OUT_CH; k++) {
        float a[8], b[4];
        #pragma unroll
        for (int i = 0; i < 8; i += 4)
            *(float4*)&a[i] = *(const float4*)&As[k][tr * 8 + i];
        *(float4*)&b[0] = *(const float4*)&Bs[k][tc * 4];
        #pragma unroll
        for (int i = 0; i < 8; i++)
            #pragma unroll
            for (int j = 0; j < 4; j++) acc[i][j] = fmaf(a[i], b[j], acc[i][j]);
    }
    #pragma unroll
    for (int i = 0; i < 8; i++) {
        int gr = rowBase + tr * 8 + i;
        if (gr >= N_NODES) continue;
        *(float4*)&out[(size_t)gr * IN_CH + colBase + tc * 4] = *(float4*)&acc[i][0];
    }
}

extern "C" void kernel_launch(void* const* d_in, const int* in_sizes, int n_in,
                              void* d_out, int out_size) {
    const float* x   = (const float*)d_in[0];
    const int*   ei  = (const int*)d_in[1];
    const float* W1  = (const float*)d_in[2];
    const float* aS1 = (const float*)d_in[3];
    const float* aD1 = (const float*)d_in[4];
    const float* b1  = (const float*)d_in[5];
    const float* W2  = (const float*)d_in[6];
    const float* aS2 = (const float*)d_in[7];
    const float* aD2 = (const float*)d_in[8];
    const float* b2  = (const float*)d_in[9];
    const float* Wd  = (const float*)d_in[10];
    const float* bd  = (const float*)d_in[11];
    (void)in_sizes; (void)n_in; (void)out_size;

    float* out  = (float*)d_out;
    float* outZ = out + (size_t)N_NODES * IN_CH;

    k_zero_rowptr<<<(N_NODES + 1 + 255) / 256, 256>>>();
    k_count<<<(ET + 255) / 256, 256>>>(ei);
    k_scan<<<1, 1024>>>();
    k_scatter<<<(ET + 255) / 256, 256>>>(ei);

    {
        dim3 grid(F1 / BN, M_PAD / BM);
        k_gemm_tf32<<<grid, 256>>>(x, W1);
    }

    k_logits1<<<N_NODES, 128>>>(aS1, aD1);
    k_agg1<<<(N_NODES * 32 + 255) / 256, 256>>>(b1);

    k_gemm2_tf32<<<M_PAD / BM, 256>>>(W2);
    k_logits2<<<(N_NODES * 32 + 255) / 256, 256>>>(aS2, aD2);
    k_agg2<<<(N_NODES * 32 + 255) / 256, 256>>>(b2, outZ);

    {
        dim3 grid(IN_CH / DBN, (N_NODES + BM - 1) / BM);
        k_decodert<<<grid, 256>>>(Wd, bd, out, outZ);
    }
}

// round 10
// speedup vs baseline: 1.7577x; 1.0636x over previous
#include <cuda_runtime.h>
#include <cuda_bf16.h>
#include <cstdint>
#include <float.h>
#include <mma.h>

using namespace nvcuda;

#define N_NODES 20000
#define N_EDGES 320000
#define ET      340000
#define IN_CH   512
#define HID     128
#define HEADS   4
#define F1      512
#define OUT_CH  30
#define NEG_SLOPE 0.2f

#define M_PAD 20096
#define ZP    32

__device__ float g_h1[M_PAD * F1];
__device__ float g_agg1[N_NODES * F1];
__device__ float g_alS1[N_NODES * HEADS];
__device__ float g_alD1[N_NODES * HEADS];
__device__ float g_zpre32[M_PAD * ZP];
__device__ float g_alS2[N_NODES];
__device__ float g_alD2[N_NODES];
__device__ int   g_rowptr[N_NODES + 1];
__device__ int   g_cursor[N_NODES];
__device__ int   g_csr_src[ET];

__device__ __forceinline__ void edge_endpoints(int e, const int* __restrict__ ei,
                                               int& src, int& dst) {
    if (e < N_EDGES) { src = ei[e]; dst = ei[N_EDGES + e]; }
    else { src = e - N_EDGES; dst = src; }
}

// ================= CSR build =================
__global__ void k_zero_rowptr() {
    int i = blockIdx.x * blockDim.x + threadIdx.x;
    if (i <= N_NODES) g_rowptr[i] = 0;
}
__global__ void k_count(const int* __restrict__ ei) {
    int e = blockIdx.x * blockDim.x + threadIdx.x;
    if (e >= ET) return;
    int src, dst; edge_endpoints(e, ei, src, dst);
    (void)src;
    atomicAdd(&g_rowptr[dst + 1], 1);
}
#define SCAN_CH 20            // ceil(20001/1024)
__global__ __launch_bounds__(1024)
void k_scan() {
    __shared__ int wsum[32];
    int tid = threadIdx.x;
    int lane = tid & 31, warp = tid >> 5;
    int base = tid * SCAN_CH;
    int incl[SCAN_CH];
    int run = 0;
    #pragma unroll
    for (int i = 0; i < SCAN_CH; i++) {
        int idx = base + i;
        int v = (idx <= N_NODES) ? g_rowptr[idx] : 0;
        run += v;
        incl[i] = run;
    }
    // warp inclusive scan of chunk totals
    int ws = run;
    #pragma unroll
    for (int o = 1; o < 32; o <<= 1) {
        int t = __shfl_up_sync(0xffffffffu, ws, o);
        if (lane >= o) ws += t;
    }
    if (lane == 31) wsum[warp] = ws;
    __syncthreads();
    if (warp == 0) {
        int t = (lane < 32) ? wsum[lane] : 0;
        #pragma unroll
        for (int o = 1; o < 32; o <<= 1) {
            int u = __shfl_up_sync(0xffffffffu, t, o);
            if (lane >= o) t += u;
        }
        wsum[lane] = t;
    }
    __syncthreads();
    int offset = (ws - run) + (warp > 0 ? wsum[warp - 1] : 0);
    #pragma unroll
    for (int i = 0; i < SCAN_CH; i++) {
        int idx = base + i;
        if (idx <= N_NODES) {
            int out = incl[i] + offset;
            g_rowptr[idx] = out;
            if (idx < N_NODES) g_cursor[idx] = out;
        }
    }
}
__global__ void k_scatter(const int* __restrict__ ei) {
    int e = blockIdx.x * blockDim.x + threadIdx.x;
    if (e >= ET) return;
    int src, dst; edge_endpoints(e, ei, src, dst);
    int pos = atomicAdd(&g_cursor[dst], 1);
    g_csr_src[pos] = src;
}

// ========== GEMM1 (tf32): g_h1 = x[M,512] @ W1[512,512], 128x128 tile, prefetch ==========
#define BM 128
#define BN1 128
#define BK 16
#define LDA (BK + 4)
#define LDB1 (BN1 + 4)
__global__ __launch_bounds__(256, 2)
void k_gemm_tf32(const float* __restrict__ A, const float* __restrict__ B) {
    __shared__ float As[BM][LDA];
    __shared__ float Bs[BK][LDB1];
    const int tid = threadIdx.x;
    const int wid = tid >> 5;
    const int wm = wid >> 1;      // 0..3 -> rows of 32
    const int wn = wid & 1;       // 0..1 -> cols of 64
    const int rowBase = blockIdx.y * BM;
    const int colBase = blockIdx.x * BN1;

    wmma::fragment<wmma::accumulator, 16, 16, 8, float> acc[2][4];
    #pragma unroll
    for (int i = 0; i < 2; i++)
        #pragma unroll
        for (int j = 0; j < 4; j++) wmma::fill_fragment(acc[i][j], 0.f);

    // prefetch registers: A 2 float4, B 2 float4 per thread
    float4 pa[2], pb[2];
    const int ar = (tid * 2) >> 2;             // A row pairs: idx= tid*2+t
    // compute per-thread A/B coords once
    #pragma unroll
    for (int t = 0; t < 2; t++) {
        int idx = tid * 2 + t;
        int r = idx >> 2, c = (idx & 3) * 4;
        int gr = rowBase + r;
        pa[t] = (gr < N_NODES) ? *(const float4*)&A[(size_t)gr * IN_CH + c]
                               : make_float4(0.f, 0.f, 0.f, 0.f);
        int br = idx >> 5, bc = (idx & 31) * 4;
        pb[t] = *(const float4*)&B[(size_t)br * F1 + colBase + bc];
    }
    (void)ar;

    const int T = IN_CH / BK;
    for (int t0 = 0; t0 < T; t0++) {
        // stage prefetched tiles
        #pragma unroll
        for (int t = 0; t < 2; t++) {
            int idx = tid * 2 + t;
            int r = idx >> 2, c = (idx & 3) * 4;
            As[r][c + 0] = wmma::__float_to_tf32(pa[t].x);
            As[r][c + 1] = wmma::__float_to_tf32(pa[t].y);
            As[r][c + 2] = wmma::__float_to_tf32(pa[t].z);
            As[r][c + 3] = wmma::__float_to_tf32(pa[t].w);
            int br = idx >> 5, bc = (idx & 31) * 4;
            Bs[br][bc + 0] = wmma::__float_to_tf32(pb[t].x);
            Bs[br][bc + 1] = wmma::__float_to_tf32(pb[t].y);
            Bs[br][bc + 2] = wmma::__float_to_tf32(pb[t].z);
            Bs[br][bc + 3] = wmma::__float_to_tf32(pb[t].w);
        }
        __syncthreads();
        // prefetch next tile
        if (t0 + 1 < T) {
            int k0n = (t0 + 1) * BK;
            #pragma unroll
            for (int t = 0; t < 2; t++) {
                int idx = tid * 2 + t;
                int r = idx >> 2, c = (idx & 3) * 4;
                int gr = rowBase + r;
                pa[t] = (gr < N_NODES) ? *(const float4*)&A[(size_t)gr * IN_CH + k0n + c]
                                       : make_float4(0.f, 0.f, 0.f, 0.f);
                int br = idx >> 5, bc = (idx & 31) * 4;
                pb[t] = *(const float4*)&B[(size_t)(k0n + br) * F1 + colBase + bc];
            }
        }
        #pragma unroll
        for (int kk = 0; kk < BK; kk += 8) {
            wmma::fragment<wmma::matrix_a, 16, 16, 8, wmma::precision::tf32, wmma::row_major> fa[2];
            wmma::fragment<wmma::matrix_b, 16, 16, 8, wmma::precision::tf32, wmma::row_major> fb[4];
            #pragma unroll
            for (int i = 0; i < 2; i++)
                wmma::load_matrix_sync(fa[i], &As[wm * 32 + i * 16][kk], LDA);
            #pragma unroll
            for (int j = 0; j < 4; j++)
                wmma::load_matrix_sync(fb[j], &Bs[kk][wn * 64 + j * 16], LDB1);
            #pragma unroll
            for (int i = 0; i < 2; i++)
                #pragma unroll
                for (int j = 0; j < 4; j++)
                    wmma::mma_sync(acc[i][j], fa[i], fb[j], acc[i][j]);
        }
        __syncthreads();
    }
    #pragma unroll
    for (int i = 0; i < 2; i++)
        #pragma unroll
        for (int j = 0; j < 4; j++) {
            int r = rowBase + wm * 32 + i * 16;
            int c = colBase + wn * 64 + j * 16;
            wmma::store_matrix_sync(&g_h1[(size_t)r * F1 + c], acc[i][j], F1,
                                    wmma::mem_row_major);
        }
}

// ========== GEMM2 (tf32): g_zpre32 = agg1[M,512] @ W2pad[512,32] ==========
#define BN2 32
#define LDB2 (BN2 + 4)
__global__ __launch_bounds__(256, 2)
void k_gemm2_tf32(const float* __restrict__ W2) {
    __shared__ float As[BM][LDA];
    __shared__ float Bs[BK][LDB2];
    const int tid = threadIdx.x;
    const int wid = tid >> 5;
    const int wm = wid >> 1;
    const int wn = wid & 1;
    const int rowBase = blockIdx.x * BM;

    wmma::fragment<wmma::accumulator, 16, 16, 8, float> acc[2];
    wmma::fill_fragment(acc[0], 0.f);
    wmma::fill_fragment(acc[1], 0.f);

    for (int k0 = 0; k0 < F1; k0 += BK) {
        #pragma unroll
        for (int t = 0; t < 2; t++) {
            int idx = tid * 2 + t;
            int r = idx >> 2;
            int c = (idx & 3) * 4;
            int gr = rowBase + r;
            float4 v = make_float4(0.f, 0.f, 0.f, 0.f);
            if (gr < N_NODES) v = *(const float4*)&g_agg1[(size_t)gr * F1 + k0 + c];
            As[r][c + 0] = wmma::__float_to_tf32(v.x);
            As[r][c + 1] = wmma::__float_to_tf32(v.y);
            As[r][c + 2] = wmma::__float_to_tf32(v.z);
            As[r][c + 3] = wmma::__float_to_tf32(v.w);
        }
        {
            #pragma unroll
            for (int t = 0; t < 2; t++) {
                int idx = tid * 2 + t;
                int r = idx >> 5;
                int c = idx & 31;
                float v = (c < OUT_CH) ? W2[(size_t)(k0 + r) * OUT_CH + c] : 0.f;
                Bs[r][c] = wmma::__float_to_tf32(v);
            }
        }
        __syncthreads();
        #pragma unroll
        for (int kk = 0; kk < BK; kk += 8) {
            wmma::fragment<wmma::matrix_a, 16, 16, 8, wmma::precision::tf32, wmma::row_major> fa[2];
            wmma::fragment<wmma::matrix_b, 16, 16, 8, wmma::precision::tf32, wmma::row_major> fb;
            #pragma unroll
            for (int i = 0; i < 2; i++)
                wmma::load_matrix_sync(fa[i], &As[wm * 32 + i * 16][kk], LDA);
            wmma::load_matrix_sync(fb, &Bs[kk][wn * 16], LDB2);
            #pragma unroll
            for (int i = 0; i < 2; i++)
                wmma::mma_sync(acc[i], fa[i], fb, acc[i]);
        }
        __syncthreads();
    }
    #pragma unroll
    for (int i = 0; i < 2; i++) {
        int r = rowBase + wm * 32 + i * 16;
        int c = wn * 16;
        wmma::store_matrix_sync(&g_zpre32[(size_t)r * ZP + c], acc[i], ZP,
                                wmma::mem_row_major);
    }
}

// ================= logits2: warp per node =================
__global__ __launch_bounds__(256)
void k_logits2(const float* __restrict__ aS2, const float* __restrict__ aD2) {
    int warp = (blockIdx.x * blockDim.x + threadIdx.x) >> 5;
    int lane = threadIdx.x & 31;
    if (warp >= N_NODES) return;
    float z = (lane < OUT_CH) ? g_zpre32[(size_t)warp * ZP + lane] : 0.f;
    float ps = (lane < OUT_CH) ? z * aS2[lane] : 0.f;
    float pd = (lane < OUT_CH) ? z * aD2[lane] : 0.f;
    #pragma unroll
    for (int o = 16; o > 0; o >>= 1) {
        ps += __shfl_down_sync(0xffffffffu, ps, o);
        pd += __shfl_down_sync(0xffffffffu, pd, o);
    }
    if (lane == 0) { g_alS2[warp] = ps; g_alD2[warp] = pd; }
}

// ================= layer 1 attention logits per node =================
__global__ void k_logits1(const float* __restrict__ aS, const float* __restrict__ aD) {
    int n = blockIdx.x;
    int w = threadIdx.x >> 5, lane = threadIdx.x & 31;
    const float* hr = g_h1 + (size_t)n * F1 + w * HID;
    const float* av = aS + w * HID;
    const float* dv = aD + w * HID;
    float s = 0.f, d = 0.f;
    #pragma unroll
    for (int i = 0; i < 4; i++) {
        float hv = hr[lane + i * 32];
        s = fmaf(hv, av[lane + i * 32], s);
        d = fmaf(hv, dv[lane + i * 32], d);
    }
    #pragma unroll
    for (int o = 16; o > 0; o >>= 1) {
        s += __shfl_down_sync(0xffffffffu, s, o);
        d += __shfl_down_sync(0xffffffffu, d, o);
    }
    if (lane == 0) { g_alS1[n * HEADS + w] = s; g_alD1[n * HEADS + w] = d; }
}

// ================= layer 1 fused softmax + aggregate + bias + ELU =================
__global__ __launch_bounds__(256)
void k_agg1(const float* __restrict__ b1) {
    int warp = (blockIdx.x * blockDim.x + threadIdx.x) >> 5;
    int lane = threadIdx.x & 31;
    if (warp >= N_NODES) return;
    int n = warp;
    int beg = g_rowptr[n], end = g_rowptr[n + 1];
    float4 ad = *(const float4*)&g_alD1[n * 4];

    float4 den = make_float4(0.f, 0.f, 0.f, 0.f);
    for (int e = beg + lane; e < end; e += 32) {
        int src = g_csr_src[e];
        float4 s = *(const float4*)&g_alS1[src * 4];
        float v;
        v = s.x + ad.x; den.x += __expf(v > 0.f ? v : NEG_SLOPE * v);
        v = s.y + ad.y; den.y += __expf(v > 0.f ? v : NEG_SLOPE * v);
        v = s.z + ad.z; den.z += __expf(v > 0.f ? v : NEG_SLOPE * v);
        v = s.w + ad.w; den.w += __expf(v > 0.f ? v : NEG_SLOPE * v);
    }
    #pragma unroll
    for (int o = 16; o > 0; o >>= 1) {
        den.x += __shfl_xor_sync(0xffffffffu, den.x, o);
        den.y += __shfl_xor_sync(0xffffffffu, den.y, o);
        den.z += __shfl_xor_sync(0xffffffffu, den.z, o);
        den.w += __shfl_xor_sync(0xffffffffu, den.w, o);
    }
    float r0 = 1.f / den.x, r1 = 1.f / den.y, r2 = 1.f / den.z, r3 = 1.f / den.w;

    float4 a0 = make_float4(0.f, 0.f, 0.f, 0.f);
    float4 a1 = a0, a2 = a0, a3 = a0;
    for (int e = beg; e < end; e++) {
        int src = g_csr_src[e];
        float4 s = *(const float4*)&g_alS1[src * 4];
        float v, w0, w1, w2, w3;
        v = s.x + ad.x; w0 = __expf(v > 0.f ? v : NEG_SLOPE * v) * r0;
        v = s.y + ad.y; w1 = __expf(v > 0.f ? v : NEG_SLOPE * v) * r1;
        v = s.z + ad.z; w2 = __expf(v > 0.f ? v : NEG_SLOPE * v) * r2;
        v = s.w + ad.w; w3 = __expf(v > 0.f ? v : NEG_SLOPE * v) * r3;
        const float4* hp = (const float4*)&g_h1[(size_t)src * F1];
        float4 h;
        h = hp[lane];      a0.x = fmaf(w0, h.x, a0.x); a0.y = fmaf(w0, h.y, a0.y); a0.z = fmaf(w0, h.z, a0.z); a0.w = fmaf(w0, h.w, a0.w);
        h = hp[32 + lane]; a1.x = fmaf(w1, h.x, a1.x); a1.y = fmaf(w1, h.y, a1.y); a1.z = fmaf(w1, h.z, a1.z); a1.w = fmaf(w1, h.w, a1.w);
        h = hp[64 + lane]; a2.x = fmaf(w2, h.x, a2.x); a2.y = fmaf(w2, h.y, a2.y); a2.z = fmaf(w2, h.z, a2.z); a2.w = fmaf(w2, h.w, a2.w);
        h = hp[96 + lane]; a3.x = fmaf(w3, h.x, a3.x); a3.y = fmaf(w3, h.y, a3.y); a3.z = fmaf(w3, h.z, a3.z); a3.w = fmaf(w3, h.w, a3.w);
    }
    float* outp = &g_agg1[(size_t)n * F1];
    float4 acc[4] = { a0, a1, a2, a3 };
    #pragma unroll
    for (int h = 0; h < 4; h++) {
        float4 bb = *(const float4*)&b1[h * HID + lane * 4];
        float4 v = acc[h];
        v.x += bb.x; v.y += bb.y; v.z += bb.z; v.w += bb.w;
        v.x = v.x > 0.f ? v.x : expm1f(v.x);
        v.y = v.y > 0.f ? v.y : expm1f(v.y);
        v.z = v.z > 0.f ? v.z : expm1f(v.z);
        v.w = v.w > 0.f ? v.w : expm1f(v.w);
        *(float4*)&outp[h * HID + lane * 4] = v;
    }
}

// ================= layer 2 fused softmax + aggregate + bias -> outZ =================
__global__ __launch_bounds__(256)
void k_agg2(const float* __restrict__ b2, float* __restrict__ outZ) {
    int warp = (blockIdx.x * blockDim.x + threadIdx.x) >> 5;
    int lane = threadIdx.x & 31;
    if (warp >= N_NODES) return;
    int n = warp;
    int beg = g_rowptr[n], end = g_rowptr[n + 1];
    float ad = g_alD2[n];

    float den = 0.f;
    for (int e = beg + lane; e < end; e += 32) {
        int src = g_csr_src[e];
        float v = g_alS2[src] + ad;
        den += __expf(v > 0.f ? v : NEG_SLOPE * v);
    }
    #pragma unroll
    for (int o = 16; o > 0; o >>= 1) den += __shfl_xor_sync(0xffffffffu, den, o);
    float rden = 1.f / den;

    float acc = 0.f;
    for (int e = beg; e < end; e++) {
        int src = g_csr_src[e];
        float v = g_alS2[src] + ad;
        float alpha = __expf(v > 0.f ? v : NEG_SLOPE * v) * rden;
        if (lane < OUT_CH) acc = fmaf(alpha, g_zpre32[(size_t)src * ZP + lane], acc);
    }
    if (lane < OUT_CH) outZ[n * OUT_CH + lane] = acc + b2[lane];
}

// ================= decoder tiled: out = z[M,30] @ Wd[30,512] + bd =================
#define DBN 64
__global__ __launch_bounds__(256, 2)
void k_decodert(const float* __restrict__ Wd, const float* __restrict__ bd,
                float* __restrict__ out, const float* __restrict__ z) {
    __shared__ float As[32][BM + 4];
    __shared__ float Bs[32][DBN];
    const int tid = threadIdx.x;
    const int tr = tid >> 4;
    const int tc = tid & 15;
    const int rowBase = blockIdx.y * BM;
    const int colBase = blockIdx.x * DBN;

    for (int idx = tid; idx < BM * 32; idx += 256) {
        int r = idx >> 5;
        int k = idx & 31;
        int gr = rowBase + r;
        float v = 0.f;
        if (k < OUT_CH && gr < N_NODES) v = z[(size_t)gr * OUT_CH + k];
        As[k][r] = v;
    }
    for (int idx = tid; idx < 32 * DBN; idx += 256) {
        int k = idx >> 6;
        int c = idx & 63;
        Bs[k][c] = (k < OUT_CH) ? Wd[(size_t)k * IN_CH + colBase + c] : 0.f;
    }
    __syncthreads();

    float acc[8][4];
    {
        float4 bb = *(const float4*)&bd[colBase + tc * 4];
        #pragma unroll
        for (int i = 0; i < 8; i++) {
            acc[i][0] = bb.x; acc[i][1] = bb.y; acc[i][2] = bb.z; acc[i][3] = bb.w;
        }
    }
    #pragma unroll
    for (int k = 0; k < OUT_CH; k++) {
        float a[8], b[4];
        #pragma unroll
        for (int i = 0; i < 8; i += 4)
            *(float4*)&a[i] = *(const float4*)&As[k][tr * 8 + i];
        *(float4*)&b[0] = *(const float4*)&Bs[k][tc * 4];
        #pragma unroll
        for (int i = 0; i < 8; i++)
            #pragma unroll
            for (int j = 0; j < 4; j++) acc[i][j] = fmaf(a[i], b[j], acc[i][j]);
    }
    #pragma unroll
    for (int i = 0; i < 8; i++) {
        int gr = rowBase + tr * 8 + i;
        if (gr >= N_NODES) continue;
        *(float4*)&out[(size_t)gr * IN_CH + colBase + tc * 4] = *(float4*)&acc[i][0];
    }
}

extern "C" void kernel_launch(void* const* d_in, const int* in_sizes, int n_in,
                              void* d_out, int out_size) {
    const float* x   = (const float*)d_in[0];
    const int*   ei  = (const int*)d_in[1];
    const float* W1  = (const float*)d_in[2];
    const float* aS1 = (const float*)d_in[3];
    const float* aD1 = (const float*)d_in[4];
    const float* b1  = (const float*)d_in[5];
    const float* W2  = (const float*)d_in[6];
    const float* aS2 = (const float*)d_in[7];
    const float* aD2 = (const float*)d_in[8];
    const float* b2  = (const float*)d_in[9];
    const float* Wd  = (const float*)d_in[10];
    const float* bd  = (const float*)d_in[11];
    (void)in_sizes; (void)n_in; (void)out_size;

    float* out  = (float*)d_out;
    float* outZ = out + (size_t)N_NODES * IN_CH;

    k_zero_rowptr<<<(N_NODES + 1 + 255) / 256, 256>>>();
    k_count<<<(ET + 255) / 256, 256>>>(ei);
    k_scan<<<1, 1024>>>();
    k_scatter<<<(ET + 255) / 256, 256>>>(ei);

    {
        dim3 grid(F1 / BN1, M_PAD / BM);
        k_gemm_tf32<<<grid, 256>>>(x, W1);
    }

    k_logits1<<<N_NODES, 128>>>(aS1, aD1);
    k_agg1<<<(N_NODES * 32 + 255) / 256, 256>>>(b1);

    k_gemm2_tf32<<<M_PAD / BM, 256>>>(W2);
    k_logits2<<<(N_NODES * 32 + 255) / 256, 256>>>(aS2, aD2);
    k_agg2<<<(N_NODES * 32 + 255) / 256, 256>>>(b2, outZ);

    {
        dim3 grid(IN_CH / DBN, (N_NODES + BM - 1) / BM);
        k_decodert<<<grid, 256>>>(Wd, bd, out, outZ);
    }
}

// round 11
// speedup vs baseline: 1.8635x; 1.0602x over previous
#include <cuda_runtime.h>
#include <cuda_bf16.h>
#include <cstdint>
#include <float.h>
#include <mma.h>

using namespace nvcuda;

#define N_NODES 20000
#define N_EDGES 320000
#define ET      340000
#define IN_CH   512
#define HID     128
#define HEADS   4
#define F1      512
#define OUT_CH  30
#define NEG_SLOPE 0.2f

#define M_PAD 20096
#define ZP    32

__device__ float g_h1[M_PAD * F1];
__device__ float g_agg1[N_NODES * F1];
__device__ float g_alS1[N_NODES * HEADS];
__device__ float g_alD1[N_NODES * HEADS];
__device__ float g_zpre32[M_PAD * ZP];
__device__ float g_alS2[N_NODES];
__device__ float g_alD2[N_NODES];
__device__ int   g_rowptr[N_NODES + 1];
__device__ int   g_cursor[N_NODES];
__device__ int   g_csr_src[ET];

__device__ __forceinline__ void edge_endpoints(int e, const int* __restrict__ ei,
                                               int& src, int& dst) {
    if (e < N_EDGES) { src = ei[e]; dst = ei[N_EDGES + e]; }
    else { src = e - N_EDGES; dst = src; }
}

// ================= CSR build =================
__global__ void k_zero_rowptr() {
    int i = blockIdx.x * blockDim.x + threadIdx.x;
    if (i <= N_NODES) g_rowptr[i] = 0;
}
__global__ void k_count(const int* __restrict__ ei) {
    int e = blockIdx.x * blockDim.x + threadIdx.x;
    if (e >= ET) return;
    int src, dst; edge_endpoints(e, ei, src, dst);
    (void)src;
    atomicAdd(&g_rowptr[dst + 1], 1);
}
#define SCAN_CH 20
__global__ __launch_bounds__(1024)
void k_scan() {
    __shared__ int wsum[32];
    int tid = threadIdx.x;
    int lane = tid & 31, warp = tid >> 5;
    int base = tid * SCAN_CH;
    int incl[SCAN_CH];
    int run = 0;
    #pragma unroll
    for (int i = 0; i < SCAN_CH; i++) {
        int idx = base + i;
        int v = (idx <= N_NODES) ? g_rowptr[idx] : 0;
        run += v;
        incl[i] = run;
    }
    int ws = run;
    #pragma unroll
    for (int o = 1; o < 32; o <<= 1) {
        int t = __shfl_up_sync(0xffffffffu, ws, o);
        if (lane >= o) ws += t;
    }
    if (lane == 31) wsum[warp] = ws;
    __syncthreads();
    if (warp == 0) {
        int t = (lane < 32) ? wsum[lane] : 0;
        #pragma unroll
        for (int o = 1; o < 32; o <<= 1) {
            int u = __shfl_up_sync(0xffffffffu, t, o);
            if (lane >= o) t += u;
        }
        wsum[lane] = t;
    }
    __syncthreads();
    int offset = (ws - run) + (warp > 0 ? wsum[warp - 1] : 0);
    #pragma unroll
    for (int i = 0; i < SCAN_CH; i++) {
        int idx = base + i;
        if (idx <= N_NODES) {
            int out = incl[i] + offset;
            g_rowptr[idx] = out;
            if (idx < N_NODES) g_cursor[idx] = out;
        }
    }
}
__global__ void k_scatter(const int* __restrict__ ei) {
    int e = blockIdx.x * blockDim.x + threadIdx.x;
    if (e >= ET) return;
    int src, dst; edge_endpoints(e, ei, src, dst);
    int pos = atomicAdd(&g_cursor[dst], 1);
    g_csr_src[pos] = src;
}

// ========== GEMM1 (tf32): g_h1 = x @ W1, 128x128 tile, prefetch ==========
#define BM 128
#define BN1 128
#define BK 16
#define LDA (BK + 4)
#define LDB1 (BN1 + 4)
__global__ __launch_bounds__(256, 2)
void k_gemm_tf32(const float* __restrict__ A, const float* __restrict__ B) {
    __shared__ float As[BM][LDA];
    __shared__ float Bs[BK][LDB1];
    const int tid = threadIdx.x;
    const int wid = tid >> 5;
    const int wm = wid >> 1;
    const int wn = wid & 1;
    const int rowBase = blockIdx.y * BM;
    const int colBase = blockIdx.x * BN1;

    wmma::fragment<wmma::accumulator, 16, 16, 8, float> acc[2][4];
    #pragma unroll
    for (int i = 0; i < 2; i++)
        #pragma unroll
        for (int j = 0; j < 4; j++) wmma::fill_fragment(acc[i][j], 0.f);

    float4 pa[2], pb[2];
    #pragma unroll
    for (int t = 0; t < 2; t++) {
        int idx = tid * 2 + t;
        int r = idx >> 2, c = (idx & 3) * 4;
        int gr = rowBase + r;
        pa[t] = (gr < N_NODES) ? *(const float4*)&A[(size_t)gr * IN_CH + c]
                               : make_float4(0.f, 0.f, 0.f, 0.f);
        int br = idx >> 5, bc = (idx & 31) * 4;
        pb[t] = *(const float4*)&B[(size_t)br * F1 + colBase + bc];
    }

    const int T = IN_CH / BK;
    for (int t0 = 0; t0 < T; t0++) {
        #pragma unroll
        for (int t = 0; t < 2; t++) {
            int idx = tid * 2 + t;
            int r = idx >> 2, c = (idx & 3) * 4;
            As[r][c + 0] = wmma::__float_to_tf32(pa[t].x);
            As[r][c + 1] = wmma::__float_to_tf32(pa[t].y);
            As[r][c + 2] = wmma::__float_to_tf32(pa[t].z);
            As[r][c + 3] = wmma::__float_to_tf32(pa[t].w);
            int br = idx >> 5, bc = (idx & 31) * 4;
            Bs[br][bc + 0] = wmma::__float_to_tf32(pb[t].x);
            Bs[br][bc + 1] = wmma::__float_to_tf32(pb[t].y);
            Bs[br][bc + 2] = wmma::__float_to_tf32(pb[t].z);
            Bs[br][bc + 3] = wmma::__float_to_tf32(pb[t].w);
        }
        __syncthreads();
        if (t0 + 1 < T) {
            int k0n = (t0 + 1) * BK;
            #pragma unroll
            for (int t = 0; t < 2; t++) {
                int idx = tid * 2 + t;
                int r = idx >> 2, c = (idx & 3) * 4;
                int gr = rowBase + r;
                pa[t] = (gr < N_NODES) ? *(const float4*)&A[(size_t)gr * IN_CH + k0n + c]
                                       : make_float4(0.f, 0.f, 0.f, 0.f);
                int br = idx >> 5, bc = (idx & 31) * 4;
                pb[t] = *(const float4*)&B[(size_t)(k0n + br) * F1 + colBase + bc];
            }
        }
        #pragma unroll
        for (int kk = 0; kk < BK; kk += 8) {
            wmma::fragment<wmma::matrix_a, 16, 16, 8, wmma::precision::tf32, wmma::row_major> fa[2];
            wmma::fragment<wmma::matrix_b, 16, 16, 8, wmma::precision::tf32, wmma::row_major> fb[4];
            #pragma unroll
            for (int i = 0; i < 2; i++)
                wmma::load_matrix_sync(fa[i], &As[wm * 32 + i * 16][kk], LDA);
            #pragma unroll
            for (int j = 0; j < 4; j++)
                wmma::load_matrix_sync(fb[j], &Bs[kk][wn * 64 + j * 16], LDB1);
            #pragma unroll
            for (int i = 0; i < 2; i++)
                #pragma unroll
                for (int j = 0; j < 4; j++)
                    wmma::mma_sync(acc[i][j], fa[i], fb[j], acc[i][j]);
        }
        __syncthreads();
    }
    #pragma unroll
    for (int i = 0; i < 2; i++)
        #pragma unroll
        for (int j = 0; j < 4; j++) {
            int r = rowBase + wm * 32 + i * 16;
            int c = colBase + wn * 64 + j * 16;
            wmma::store_matrix_sync(&g_h1[(size_t)r * F1 + c], acc[i][j], F1,
                                    wmma::mem_row_major);
        }
}

// ========== GEMM2 (tf32): g_zpre32 = agg1 @ W2pad ==========
#define BN2 32
#define LDB2 (BN2 + 4)
__global__ __launch_bounds__(256, 2)
void k_gemm2_tf32(const float* __restrict__ W2) {
    __shared__ float As[BM][LDA];
    __shared__ float Bs[BK][LDB2];
    const int tid = threadIdx.x;
    const int wid = tid >> 5;
    const int wm = wid >> 1;
    const int wn = wid & 1;
    const int rowBase = blockIdx.x * BM;

    wmma::fragment<wmma::accumulator, 16, 16, 8, float> acc[2];
    wmma::fill_fragment(acc[0], 0.f);
    wmma::fill_fragment(acc[1], 0.f);

    for (int k0 = 0; k0 < F1; k0 += BK) {
        #pragma unroll
        for (int t = 0; t < 2; t++) {
            int idx = tid * 2 + t;
            int r = idx >> 2;
            int c = (idx & 3) * 4;
            int gr = rowBase + r;
            float4 v = make_float4(0.f, 0.f, 0.f, 0.f);
            if (gr < N_NODES) v = *(const float4*)&g_agg1[(size_t)gr * F1 + k0 + c];
            As[r][c + 0] = wmma::__float_to_tf32(v.x);
            As[r][c + 1] = wmma::__float_to_tf32(v.y);
            As[r][c + 2] = wmma::__float_to_tf32(v.z);
            As[r][c + 3] = wmma::__float_to_tf32(v.w);
        }
        {
            #pragma unroll
            for (int t = 0; t < 2; t++) {
                int idx = tid * 2 + t;
                int r = idx >> 5;
                int c = idx & 31;
                float v = (c < OUT_CH) ? W2[(size_t)(k0 + r) * OUT_CH + c] : 0.f;
                Bs[r][c] = wmma::__float_to_tf32(v);
            }
        }
        __syncthreads();
        #pragma unroll
        for (int kk = 0; kk < BK; kk += 8) {
            wmma::fragment<wmma::matrix_a, 16, 16, 8, wmma::precision::tf32, wmma::row_major> fa[2];
            wmma::fragment<wmma::matrix_b, 16, 16, 8, wmma::precision::tf32, wmma::row_major> fb;
            #pragma unroll
            for (int i = 0; i < 2; i++)
                wmma::load_matrix_sync(fa[i], &As[wm * 32 + i * 16][kk], LDA);
            wmma::load_matrix_sync(fb, &Bs[kk][wn * 16], LDB2);
            #pragma unroll
            for (int i = 0; i < 2; i++)
                wmma::mma_sync(acc[i], fa[i], fb, acc[i]);
        }
        __syncthreads();
    }
    #pragma unroll
    for (int i = 0; i < 2; i++) {
        int r = rowBase + wm * 32 + i * 16;
        int c = wn * 16;
        wmma::store_matrix_sync(&g_zpre32[(size_t)r * ZP + c], acc[i], ZP,
                                wmma::mem_row_major);
    }
}

// ================= logits2: warp per node =================
__global__ __launch_bounds__(256)
void k_logits2(const float* __restrict__ aS2, const float* __restrict__ aD2) {
    int warp = (blockIdx.x * blockDim.x + threadIdx.x) >> 5;
    int lane = threadIdx.x & 31;
    if (warp >= N_NODES) return;
    float z = (lane < OUT_CH) ? g_zpre32[(size_t)warp * ZP + lane] : 0.f;
    float ps = (lane < OUT_CH) ? z * aS2[lane] : 0.f;
    float pd = (lane < OUT_CH) ? z * aD2[lane] : 0.f;
    #pragma unroll
    for (int o = 16; o > 0; o >>= 1) {
        ps += __shfl_down_sync(0xffffffffu, ps, o);
        pd += __shfl_down_sync(0xffffffffu, pd, o);
    }
    if (lane == 0) { g_alS2[warp] = ps; g_alD2[warp] = pd; }
}

// ================= layer 1 attention logits per node =================
__global__ void k_logits1(const float* __restrict__ aS, const float* __restrict__ aD) {
    int n = blockIdx.x;
    int w = threadIdx.x >> 5, lane = threadIdx.x & 31;
    const float* hr = g_h1 + (size_t)n * F1 + w * HID;
    const float* av = aS + w * HID;
    const float* dv = aD + w * HID;
    float s = 0.f, d = 0.f;
    #pragma unroll
    for (int i = 0; i < 4; i++) {
        float hv = hr[lane + i * 32];
        s = fmaf(hv, av[lane + i * 32], s);
        d = fmaf(hv, dv[lane + i * 32], d);
    }
    #pragma unroll
    for (int o = 16; o > 0; o >>= 1) {
        s += __shfl_down_sync(0xffffffffu, s, o);
        d += __shfl_down_sync(0xffffffffu, d, o);
    }
    if (lane == 0) { g_alS1[n * HEADS + w] = s; g_alD1[n * HEADS + w] = d; }
}

// ======= layer 1 fused softmax + aggregate + bias + ELU (2-edge unroll) =======
__device__ __forceinline__ void edge_w4(const float4 s, const float4 ad,
                                        float r0, float r1, float r2, float r3,
                                        float& w0, float& w1, float& w2, float& w3) {
    float v;
    v = s.x + ad.x; w0 = __expf(v > 0.f ? v : NEG_SLOPE * v) * r0;
    v = s.y + ad.y; w1 = __expf(v > 0.f ? v : NEG_SLOPE * v) * r1;
    v = s.z + ad.z; w2 = __expf(v > 0.f ? v : NEG_SLOPE * v) * r2;
    v = s.w + ad.w; w3 = __expf(v > 0.f ? v : NEG_SLOPE * v) * r3;
}

__global__ __launch_bounds__(256)
void k_agg1(const float* __restrict__ b1) {
    int warp = (blockIdx.x * blockDim.x + threadIdx.x) >> 5;
    int lane = threadIdx.x & 31;
    if (warp >= N_NODES) return;
    int n = warp;
    int beg = g_rowptr[n], end = g_rowptr[n + 1];
    float4 ad = *(const float4*)&g_alD1[n * 4];

    float4 den = make_float4(0.f, 0.f, 0.f, 0.f);
    for (int e = beg + lane; e < end; e += 32) {
        int src = g_csr_src[e];
        float4 s = *(const float4*)&g_alS1[src * 4];
        float v;
        v = s.x + ad.x; den.x += __expf(v > 0.f ? v : NEG_SLOPE * v);
        v = s.y + ad.y; den.y += __expf(v > 0.f ? v : NEG_SLOPE * v);
        v = s.z + ad.z; den.z += __expf(v > 0.f ? v : NEG_SLOPE * v);
        v = s.w + ad.w; den.w += __expf(v > 0.f ? v : NEG_SLOPE * v);
    }
    #pragma unroll
    for (int o = 16; o > 0; o >>= 1) {
        den.x += __shfl_xor_sync(0xffffffffu, den.x, o);
        den.y += __shfl_xor_sync(0xffffffffu, den.y, o);
        den.z += __shfl_xor_sync(0xffffffffu, den.z, o);
        den.w += __shfl_xor_sync(0xffffffffu, den.w, o);
    }
    float r0 = 1.f / den.x, r1 = 1.f / den.y, r2 = 1.f / den.z, r3 = 1.f / den.w;

    // two independent accumulator sets for the 2-edge unroll
    float4 a0 = make_float4(0.f, 0.f, 0.f, 0.f), a1 = a0, a2 = a0, a3 = a0;
    float4 c0 = a0, c1 = a0, c2 = a0, c3 = a0;

    int e = beg;
    for (; e + 2 <= end; e += 2) {
        int srcA = g_csr_src[e];
        int srcB = g_csr_src[e + 1];
        float4 sA = *(const float4*)&g_alS1[srcA * 4];
        float4 sB = *(const float4*)&g_alS1[srcB * 4];
        float wA0, wA1, wA2, wA3, wB0, wB1, wB2, wB3;
        edge_w4(sA, ad, r0, r1, r2, r3, wA0, wA1, wA2, wA3);
        edge_w4(sB, ad, r0, r1, r2, r3, wB0, wB1, wB2, wB3);
        const float4* hpA = (const float4*)&g_h1[(size_t)srcA * F1];
        const float4* hpB = (const float4*)&g_h1[(size_t)srcB * F1];
        float4 hA0 = hpA[lane],      hB0 = hpB[lane];
        float4 hA1 = hpA[32 + lane], hB1 = hpB[32 + lane];
        float4 hA2 = hpA[64 + lane], hB2 = hpB[64 + lane];
        float4 hA3 = hpA[96 + lane], hB3 = hpB[96 + lane];
        a0.x = fmaf(wA0, hA0.x, a0.x); a0.y = fmaf(wA0, hA0.y, a0.y); a0.z = fmaf(wA0, hA0.z, a0.z); a0.w = fmaf(wA0, hA0.w, a0.w);
        c0.x = fmaf(wB0, hB0.x, c0.x); c0.y = fmaf(wB0, hB0.y, c0.y); c0.z = fmaf(wB0, hB0.z, c0.z); c0.w = fmaf(wB0, hB0.w, c0.w);
        a1.x = fmaf(wA1, hA1.x, a1.x); a1.y = fmaf(wA1, hA1.y, a1.y); a1.z = fmaf(wA1, hA1.z, a1.z); a1.w = fmaf(wA1, hA1.w, a1.w);
        c1.x = fmaf(wB1, hB1.x, c1.x); c1.y = fmaf(wB1, hB1.y, c1.y); c1.z = fmaf(wB1, hB1.z, c1.z); c1.w = fmaf(wB1, hB1.w, c1.w);
        a2.x = fmaf(wA2, hA2.x, a2.x); a2.y = fmaf(wA2, hA2.y, a2.y); a2.z = fmaf(wA2, hA2.z, a2.z); a2.w = fmaf(wA2, hA2.w, a2.w);
        c2.x = fmaf(wB2, hB2.x, c2.x); c2.y = fmaf(wB2, hB2.y, c2.y); c2.z = fmaf(wB2, hB2.z, c2.z); c2.w = fmaf(wB2, hB2.w, c2.w);
        a3.x = fmaf(wA3, hA3.x, a3.x); a3.y = fmaf(wA3, hA3.y, a3.y); a3.z = fmaf(wA3, hA3.z, a3.z); a3.w = fmaf(wA3, hA3.w, a3.w);
        c3.x = fmaf(wB3, hB3.x, c3.x); c3.y = fmaf(wB3, hB3.y, c3.y); c3.z = fmaf(wB3, hB3.z, c3.z); c3.w = fmaf(wB3, hB3.w, c3.w);
    }
    if (e < end) {
        int src = g_csr_src[e];
        float4 s = *(const float4*)&g_alS1[src * 4];
        float w0, w1, w2, w3;
        edge_w4(s, ad, r0, r1, r2, r3, w0, w1, w2, w3);
        const float4* hp = (const float4*)&g_h1[(size_t)src * F1];
        float4 h;
        h = hp[lane];      a0.x = fmaf(w0, h.x, a0.x); a0.y = fmaf(w0, h.y, a0.y); a0.z = fmaf(w0, h.z, a0.z); a0.w = fmaf(w0, h.w, a0.w);
        h = hp[32 + lane]; a1.x = fmaf(w1, h.x, a1.x); a1.y = fmaf(w1, h.y, a1.y); a1.z = fmaf(w1, h.z, a1.z); a1.w = fmaf(w1, h.w, a1.w);
        h = hp[64 + lane]; a2.x = fmaf(w2, h.x, a2.x); a2.y = fmaf(w2, h.y, a2.y); a2.z = fmaf(w2, h.z, a2.z); a2.w = fmaf(w2, h.w, a2.w);
        h = hp[96 + lane]; a3.x = fmaf(w3, h.x, a3.x); a3.y = fmaf(w3, h.y, a3.y); a3.z = fmaf(w3, h.z, a3.z); a3.w = fmaf(w3, h.w, a3.w);
    }
    a0.x += c0.x; a0.y += c0.y; a0.z += c0.z; a0.w += c0.w;
    a1.x += c1.x; a1.y += c1.y; a1.z += c1.z; a1.w += c1.w;
    a2.x += c2.x; a2.y += c2.y; a2.z += c2.z; a2.w += c2.w;
    a3.x += c3.x; a3.y += c3.y; a3.z += c3.z; a3.w += c3.w;

    float* outp = &g_agg1[(size_t)n * F1];
    float4 acc[4] = { a0, a1, a2, a3 };
    #pragma unroll
    for (int h = 0; h < 4; h++) {
        float4 bb = *(const float4*)&b1[h * HID + lane * 4];
        float4 v = acc[h];
        v.x += bb.x; v.y += bb.y; v.z += bb.z; v.w += bb.w;
        v.x = v.x > 0.f ? v.x : expm1f(v.x);
        v.y = v.y > 0.f ? v.y : expm1f(v.y);
        v.z = v.z > 0.f ? v.z : expm1f(v.z);
        v.w = v.w > 0.f ? v.w : expm1f(v.w);
        *(float4*)&outp[h * HID + lane * 4] = v;
    }
}

// ================= layer 2 fused softmax + aggregate + bias -> outZ =================
__global__ __launch_bounds__(256)
void k_agg2(const float* __restrict__ b2, float* __restrict__ outZ) {
    int warp = (blockIdx.x * blockDim.x + threadIdx.x) >> 5;
    int lane = threadIdx.x & 31;
    if (warp >= N_NODES) return;
    int n = warp;
    int beg = g_rowptr[n], end = g_rowptr[n + 1];
    float ad = g_alD2[n];

    float den = 0.f;
    for (int e = beg + lane; e < end; e += 32) {
        int src = g_csr_src[e];
        float v = g_alS2[src] + ad;
        den += __expf(v > 0.f ? v : NEG_SLOPE * v);
    }
    #pragma unroll
    for (int o = 16; o > 0; o >>= 1) den += __shfl_xor_sync(0xffffffffu, den, o);
    float rden = 1.f / den;

    float acc = 0.f;
    for (int e = beg; e < end; e++) {
        int src = g_csr_src[e];
        float v = g_alS2[src] + ad;
        float alpha = __expf(v > 0.f ? v : NEG_SLOPE * v) * rden;
        if (lane < OUT_CH) acc = fmaf(alpha, g_zpre32[(size_t)src * ZP + lane], acc);
    }
    if (lane < OUT_CH) outZ[n * OUT_CH + lane] = acc + b2[lane];
}

// ================= decoder tiled =================
#define DBN 64
__global__ __launch_bounds__(256, 2)
void k_decodert(const float* __restrict__ Wd, const float* __restrict__ bd,
                float* __restrict__ out, const float* __restrict__ z) {
    __shared__ float As[32][BM + 4];
    __shared__ float Bs[32][DBN];
    const int tid = threadIdx.x;
    const int tr = tid >> 4;
    const int tc = tid & 15;
    const int rowBase = blockIdx.y * BM;
    const int colBase = blockIdx.x * DBN;

    for (int idx = tid; idx < BM * 32; idx += 256) {
        int r = idx >> 5;
        int k = idx & 31;
        int gr = rowBase + r;
        float v = 0.f;
        if (k < OUT_CH && gr < N_NODES) v = z[(size_t)gr * OUT_CH + k];
        As[k][r] = v;
    }
    for (int idx = tid; idx < 32 * DBN; idx += 256) {
        int k = idx >> 6;
        int c = idx & 63;
        Bs[k][c] = (k < OUT_CH) ? Wd[(size_t)k * IN_CH + colBase + c] : 0.f;
    }
    __syncthreads();

    float acc[8][4];
    {
        float4 bb = *(const float4*)&bd[colBase + tc * 4];
        #pragma unroll
        for (int i = 0; i < 8; i++) {
            acc[i][0] = bb.x; acc[i][1] = bb.y; acc[i][2] = bb.z; acc[i][3] = bb.w;
        }
    }
    #pragma unroll
    for (int k = 0; k < OUT_CH; k++) {
        float a[8], b[4];
        #pragma unroll
        for (int i = 0; i < 8; i += 4)
            *(float4*)&a[i] = *(const float4*)&As[k][tr * 8 + i];
        *(float4*)&b[0] = *(const float4*)&Bs[k][tc * 4];
        #pragma unroll
        for (int i = 0; i < 8; i++)
            #pragma unroll
            for (int j = 0; j < 4; j++) acc[i][j] = fmaf(a[i], b[j], acc[i][j]);
    }
    #pragma unroll
    for (int i = 0; i < 8; i++) {
        int gr = rowBase + tr * 8 + i;
        if (gr >= N_NODES) continue;
        *(float4*)&out[(size_t)gr * IN_CH + colBase + tc * 4] = *(float4*)&acc[i][0];
    }
}

extern "C" void kernel_launch(void* const* d_in, const int* in_sizes, int n_in,
                              void* d_out, int out_size) {
    const float* x   = (const float*)d_in[0];
    const int*   ei  = (const int*)d_in[1];
    const float* W1  = (const float*)d_in[2];
    const float* aS1 = (const float*)d_in[3];
    const float* aD1 = (const float*)d_in[4];
    const float* b1  = (const float*)d_in[5];
    const float* W2  = (const float*)d_in[6];
    const float* aS2 = (const float*)d_in[7];
    const float* aD2 = (const float*)d_in[8];
    const float* b2  = (const float*)d_in[9];
    const float* Wd  = (const float*)d_in[10];
    const float* bd  = (const float*)d_in[11];
    (void)in_sizes; (void)n_in; (void)out_size;

    float* out  = (float*)d_out;
    float* outZ = out + (size_t)N_NODES * IN_CH;

    static cudaStream_t s2 = nullptr;
    static cudaEvent_t evFork = nullptr, evJoin = nullptr;
    if (s2 == nullptr) {
        cudaStreamCreateWithFlags(&s2, cudaStreamNonBlocking);
        cudaEventCreateWithFlags(&evFork, cudaEventDisableTiming);
        cudaEventCreateWithFlags(&evJoin, cudaEventDisableTiming);
    }

    // fork: CSR build on s2, concurrent with GEMM1 + logits1
    cudaEventRecord(evFork, 0);
    cudaStreamWaitEvent(s2, evFork, 0);
    k_zero_rowptr<<<(N_NODES + 1 + 255) / 256, 256, 0, s2>>>();
    k_count<<<(ET + 255) / 256, 256, 0, s2>>>(ei);
    k_scan<<<1, 1024, 0, s2>>>();
    k_scatter<<<(ET + 255) / 256, 256, 0, s2>>>(ei);
    cudaEventRecord(evJoin, s2);

    {
        dim3 grid(F1 / BN1, M_PAD / BM);
        k_gemm_tf32<<<grid, 256>>>(x, W1);
    }
    k_logits1<<<N_NODES, 128>>>(aS1, aD1);

    cudaStreamWaitEvent(0, evJoin, 0);

    k_agg1<<<(N_NODES * 32 + 255) / 256, 256>>>(b1);

    k_gemm2_tf32<<<M_PAD / BM, 256>>>(W2);
    k_logits2<<<(N_NODES * 32 + 255) / 256, 256>>>(aS2, aD2);
    k_agg2<<<(N_NODES * 32 + 255) / 256, 256>>>(b2, outZ);

    {
        dim3 grid(IN_CH / DBN, (N_NODES + BM - 1) / BM);
        k_decodert<<<grid, 256>>>(Wd, bd, out, outZ);
    }
}

// round 12
// speedup vs baseline: 1.9307x; 1.0361x over previous
#include <cuda_runtime.h>
#include <cuda_bf16.h>
#include <cstdint>
#include <float.h>
#include <mma.h>

using namespace nvcuda;

#define N_NODES 20000
#define N_EDGES 320000
#define ET      340000
#define IN_CH   512
#define HID     128
#define HEADS   4
#define F1      512
#define OUT_CH  30
#define NEG_SLOPE 0.2f

#define M_PAD 20096
#define ZP    32

__device__ float g_h1[M_PAD * F1];
__device__ float g_agg1[N_NODES * F1];
__device__ float g_alS1[N_NODES * HEADS];
__device__ float g_alD1[N_NODES * HEADS];
__device__ float g_zpre32[M_PAD * ZP];
__device__ float g_alS2[N_NODES];
__device__ float g_alD2[N_NODES];
__device__ int   g_rowptr[N_NODES + 1];
__device__ int   g_cursor[N_NODES];
__device__ int   g_csr_src[ET];

__device__ __forceinline__ void edge_endpoints(int e, const int* __restrict__ ei,
                                               int& src, int& dst) {
    if (e < N_EDGES) { src = ei[e]; dst = ei[N_EDGES + e]; }
    else { src = e - N_EDGES; dst = src; }
}

__device__ __forceinline__ float lrelu_exp(float v) {
    return __expf(v > 0.f ? v : NEG_SLOPE * v);
}

// ================= CSR build =================
__global__ void k_zero_rowptr() {
    int i = blockIdx.x * blockDim.x + threadIdx.x;
    if (i <= N_NODES) g_rowptr[i] = 0;
}
__global__ void k_count(const int* __restrict__ ei) {
    int e = blockIdx.x * blockDim.x + threadIdx.x;
    if (e >= ET) return;
    int src, dst; edge_endpoints(e, ei, src, dst);
    (void)src;
    atomicAdd(&g_rowptr[dst + 1], 1);
}
#define SCAN_CH 20
__global__ __launch_bounds__(1024)
void k_scan() {
    __shared__ int wsum[32];
    int tid = threadIdx.x;
    int lane = tid & 31, warp = tid >> 5;
    int base = tid * SCAN_CH;
    int incl[SCAN_CH];
    int run = 0;
    #pragma unroll
    for (int i = 0; i < SCAN_CH; i++) {
        int idx = base + i;
        int v = (idx <= N_NODES) ? g_rowptr[idx] : 0;
        run += v;
        incl[i] = run;
    }
    int ws = run;
    #pragma unroll
    for (int o = 1; o < 32; o <<= 1) {
        int t = __shfl_up_sync(0xffffffffu, ws, o);
        if (lane >= o) ws += t;
    }
    if (lane == 31) wsum[warp] = ws;
    __syncthreads();
    if (warp == 0) {
        int t = (lane < 32) ? wsum[lane] : 0;
        #pragma unroll
        for (int o = 1; o < 32; o <<= 1) {
            int u = __shfl_up_sync(0xffffffffu, t, o);
            if (lane >= o) t += u;
        }
        wsum[lane] = t;
    }
    __syncthreads();
    int offset = (ws - run) + (warp > 0 ? wsum[warp - 1] : 0);
    #pragma unroll
    for (int i = 0; i < SCAN_CH; i++) {
        int idx = base + i;
        if (idx <= N_NODES) {
            int out = incl[i] + offset;
            g_rowptr[idx] = out;
            if (idx < N_NODES) g_cursor[idx] = out;
        }
    }
}
__global__ void k_scatter(const int* __restrict__ ei) {
    int e = blockIdx.x * blockDim.x + threadIdx.x;
    if (e >= ET) return;
    int src, dst; edge_endpoints(e, ei, src, dst);
    int pos = atomicAdd(&g_cursor[dst], 1);
    g_csr_src[pos] = src;
}

// ========== GEMM1 (tf32): g_h1 = x @ W1, 128x128 tile, prefetch ==========
#define BM 128
#define BN1 128
#define BK 16
#define LDA (BK + 4)
#define LDB1 (BN1 + 4)
__global__ __launch_bounds__(256, 2)
void k_gemm_tf32(const float* __restrict__ A, const float* __restrict__ B) {
    __shared__ float As[BM][LDA];
    __shared__ float Bs[BK][LDB1];
    const int tid = threadIdx.x;
    const int wid = tid >> 5;
    const int wm = wid >> 1;
    const int wn = wid & 1;
    const int rowBase = blockIdx.y * BM;
    const int colBase = blockIdx.x * BN1;

    wmma::fragment<wmma::accumulator, 16, 16, 8, float> acc[2][4];
    #pragma unroll
    for (int i = 0; i < 2; i++)
        #pragma unroll
        for (int j = 0; j < 4; j++) wmma::fill_fragment(acc[i][j], 0.f);

    float4 pa[2], pb[2];
    #pragma unroll
    for (int t = 0; t < 2; t++) {
        int idx = tid * 2 + t;
        int r = idx >> 2, c = (idx & 3) * 4;
        int gr = rowBase + r;
        pa[t] = (gr < N_NODES) ? *(const float4*)&A[(size_t)gr * IN_CH + c]
                               : make_float4(0.f, 0.f, 0.f, 0.f);
        int br = idx >> 5, bc = (idx & 31) * 4;
        pb[t] = *(const float4*)&B[(size_t)br * F1 + colBase + bc];
    }

    const int T = IN_CH / BK;
    for (int t0 = 0; t0 < T; t0++) {
        #pragma unroll
        for (int t = 0; t < 2; t++) {
            int idx = tid * 2 + t;
            int r = idx >> 2, c = (idx & 3) * 4;
            As[r][c + 0] = wmma::__float_to_tf32(pa[t].x);
            As[r][c + 1] = wmma::__float_to_tf32(pa[t].y);
            As[r][c + 2] = wmma::__float_to_tf32(pa[t].z);
            As[r][c + 3] = wmma::__float_to_tf32(pa[t].w);
            int br = idx >> 5, bc = (idx & 31) * 4;
            Bs[br][bc + 0] = wmma::__float_to_tf32(pb[t].x);
            Bs[br][bc + 1] = wmma::__float_to_tf32(pb[t].y);
            Bs[br][bc + 2] = wmma::__float_to_tf32(pb[t].z);
            Bs[br][bc + 3] = wmma::__float_to_tf32(pb[t].w);
        }
        __syncthreads();
        if (t0 + 1 < T) {
            int k0n = (t0 + 1) * BK;
            #pragma unroll
            for (int t = 0; t < 2; t++) {
                int idx = tid * 2 + t;
                int r = idx >> 2, c = (idx & 3) * 4;
                int gr = rowBase + r;
                pa[t] = (gr < N_NODES) ? *(const float4*)&A[(size_t)gr * IN_CH + k0n + c]
                                       : make_float4(0.f, 0.f, 0.f, 0.f);
                int br = idx >> 5, bc = (idx & 31) * 4;
                pb[t] = *(const float4*)&B[(size_t)(k0n + br) * F1 + colBase + bc];
            }
        }
        #pragma unroll
        for (int kk = 0; kk < BK; kk += 8) {
            wmma::fragment<wmma::matrix_a, 16, 16, 8, wmma::precision::tf32, wmma::row_major> fa[2];
            wmma::fragment<wmma::matrix_b, 16, 16, 8, wmma::precision::tf32, wmma::row_major> fb[4];
            #pragma unroll
            for (int i = 0; i < 2; i++)
                wmma::load_matrix_sync(fa[i], &As[wm * 32 + i * 16][kk], LDA);
            #pragma unroll
            for (int j = 0; j < 4; j++)
                wmma::load_matrix_sync(fb[j], &Bs[kk][wn * 64 + j * 16], LDB1);
            #pragma unroll
            for (int i = 0; i < 2; i++)
                #pragma unroll
                for (int j = 0; j < 4; j++)
                    wmma::mma_sync(acc[i][j], fa[i], fb[j], acc[i][j]);
        }
        __syncthreads();
    }
    #pragma unroll
    for (int i = 0; i < 2; i++)
        #pragma unroll
        for (int j = 0; j < 4; j++) {
            int r = rowBase + wm * 32 + i * 16;
            int c = colBase + wn * 64 + j * 16;
            wmma::store_matrix_sync(&g_h1[(size_t)r * F1 + c], acc[i][j], F1,
                                    wmma::mem_row_major);
        }
}

// ========== GEMM2 (tf32): g_zpre32 = agg1 @ W2pad ==========
#define BN2 32
#define LDB2 (BN2 + 4)
__global__ __launch_bounds__(256, 2)
void k_gemm2_tf32(const float* __restrict__ W2) {
    __shared__ float As[BM][LDA];
    __shared__ float Bs[BK][LDB2];
    const int tid = threadIdx.x;
    const int wid = tid >> 5;
    const int wm = wid >> 1;
    const int wn = wid & 1;
    const int rowBase = blockIdx.x * BM;

    wmma::fragment<wmma::accumulator, 16, 16, 8, float> acc[2];
    wmma::fill_fragment(acc[0], 0.f);
    wmma::fill_fragment(acc[1], 0.f);

    for (int k0 = 0; k0 < F1; k0 += BK) {
        #pragma unroll
        for (int t = 0; t < 2; t++) {
            int idx = tid * 2 + t;
            int r = idx >> 2;
            int c = (idx & 3) * 4;
            int gr = rowBase + r;
            float4 v = make_float4(0.f, 0.f, 0.f, 0.f);
            if (gr < N_NODES) v = *(const float4*)&g_agg1[(size_t)gr * F1 + k0 + c];
            As[r][c + 0] = wmma::__float_to_tf32(v.x);
            As[r][c + 1] = wmma::__float_to_tf32(v.y);
            As[r][c + 2] = wmma::__float_to_tf32(v.z);
            As[r][c + 3] = wmma::__float_to_tf32(v.w);
        }
        {
            #pragma unroll
            for (int t = 0; t < 2; t++) {
                int idx = tid * 2 + t;
                int r = idx >> 5;
                int c = idx & 31;
                float v = (c < OUT_CH) ? W2[(size_t)(k0 + r) * OUT_CH + c] : 0.f;
                Bs[r][c] = wmma::__float_to_tf32(v);
            }
        }
        __syncthreads();
        #pragma unroll
        for (int kk = 0; kk < BK; kk += 8) {
            wmma::fragment<wmma::matrix_a, 16, 16, 8, wmma::precision::tf32, wmma::row_major> fa[2];
            wmma::fragment<wmma::matrix_b, 16, 16, 8, wmma::precision::tf32, wmma::row_major> fb;
            #pragma unroll
            for (int i = 0; i < 2; i++)
                wmma::load_matrix_sync(fa[i], &As[wm * 32 + i * 16][kk], LDA);
            wmma::load_matrix_sync(fb, &Bs[kk][wn * 16], LDB2);
            #pragma unroll
            for (int i = 0; i < 2; i++)
                wmma::mma_sync(acc[i], fa[i], fb, acc[i]);
        }
        __syncthreads();
    }
    #pragma unroll
    for (int i = 0; i < 2; i++) {
        int r = rowBase + wm * 32 + i * 16;
        int c = wn * 16;
        wmma::store_matrix_sync(&g_zpre32[(size_t)r * ZP + c], acc[i], ZP,
                                wmma::mem_row_major);
    }
}

// ================= logits2: warp per node =================
__global__ __launch_bounds__(256)
void k_logits2(const float* __restrict__ aS2, const float* __restrict__ aD2) {
    int warp = (blockIdx.x * blockDim.x + threadIdx.x) >> 5;
    int lane = threadIdx.x & 31;
    if (warp >= N_NODES) return;
    float z = (lane < OUT_CH) ? g_zpre32[(size_t)warp * ZP + lane] : 0.f;
    float ps = (lane < OUT_CH) ? z * aS2[lane] : 0.f;
    float pd = (lane < OUT_CH) ? z * aD2[lane] : 0.f;
    #pragma unroll
    for (int o = 16; o > 0; o >>= 1) {
        ps += __shfl_down_sync(0xffffffffu, ps, o);
        pd += __shfl_down_sync(0xffffffffu, pd, o);
    }
    if (lane == 0) { g_alS2[warp] = ps; g_alD2[warp] = pd; }
}

// ================= layer 1 attention logits per node =================
__global__ void k_logits1(const float* __restrict__ aS, const float* __restrict__ aD) {
    int n = blockIdx.x;
    int w = threadIdx.x >> 5, lane = threadIdx.x & 31;
    const float* hr = g_h1 + (size_t)n * F1 + w * HID;
    const float* av = aS + w * HID;
    const float* dv = aD + w * HID;
    float s = 0.f, d = 0.f;
    #pragma unroll
    for (int i = 0; i < 4; i++) {
        float hv = hr[lane + i * 32];
        s = fmaf(hv, av[lane + i * 32], s);
        d = fmaf(hv, dv[lane + i * 32], d);
    }
    #pragma unroll
    for (int o = 16; o > 0; o >>= 1) {
        s += __shfl_down_sync(0xffffffffu, s, o);
        d += __shfl_down_sync(0xffffffffu, d, o);
    }
    if (lane == 0) { g_alS1[n * HEADS + w] = s; g_alD1[n * HEADS + w] = d; }
}

// ======= layer 1 aggregate: warp per (node, head-pair), 4-edge unroll =======
__global__ __launch_bounds__(256)
void k_agg1(const float* __restrict__ b1) {
    int gw = (blockIdx.x * blockDim.x + threadIdx.x) >> 5;
    int lane = threadIdx.x & 31;
    if (gw >= 2 * N_NODES) return;
    int n = gw >> 1;
    int hp = gw & 1;              // head pair: heads 2hp, 2hp+1
    int beg = g_rowptr[n], end = g_rowptr[n + 1];
    float2 ad = *(const float2*)&g_alD1[n * 4 + hp * 2];

    // pass 1: denominators for the 2 heads
    float2 den = make_float2(0.f, 0.f);
    for (int e = beg + lane; e < end; e += 32) {
        int src = g_csr_src[e];
        float2 s = *(const float2*)&g_alS1[src * 4 + hp * 2];
        den.x += lrelu_exp(s.x + ad.x);
        den.y += lrelu_exp(s.y + ad.y);
    }
    #pragma unroll
    for (int o = 16; o > 0; o >>= 1) {
        den.x += __shfl_xor_sync(0xffffffffu, den.x, o);
        den.y += __shfl_xor_sync(0xffffffffu, den.y, o);
    }
    float r0 = 1.f / den.x, r1 = 1.f / den.y;

    const size_t colBase = (size_t)(hp * 2) * HID;   // byte column of head 2hp

    // pass 2: 4-edge unroll, 2 chains
    float4 a0 = make_float4(0.f, 0.f, 0.f, 0.f), a1 = a0;   // chain A: heads 2hp, 2hp+1
    float4 c0 = a0, c1 = a0;                                 // chain B
    int e = beg;
    for (; e + 4 <= end; e += 4) {
        int s0 = g_csr_src[e], s1 = g_csr_src[e + 1];
        int s2 = g_csr_src[e + 2], s3 = g_csr_src[e + 3];
        float2 l0 = *(const float2*)&g_alS1[s0 * 4 + hp * 2];
        float2 l1 = *(const float2*)&g_alS1[s1 * 4 + hp * 2];
        float2 l2 = *(const float2*)&g_alS1[s2 * 4 + hp * 2];
        float2 l3 = *(const float2*)&g_alS1[s3 * 4 + hp * 2];
        const float4* p0 = (const float4*)&g_h1[(size_t)s0 * F1 + colBase];
        const float4* p1 = (const float4*)&g_h1[(size_t)s1 * F1 + colBase];
        const float4* p2 = (const float4*)&g_h1[(size_t)s2 * F1 + colBase];
        const float4* p3 = (const float4*)&g_h1[(size_t)s3 * F1 + colBase];
        float4 h00 = p0[lane], h01 = p0[32 + lane];
        float4 h10 = p1[lane], h11 = p1[32 + lane];
        float4 h20 = p2[lane], h21 = p2[32 + lane];
        float4 h30 = p3[lane], h31 = p3[32 + lane];
        float w00 = lrelu_exp(l0.x + ad.x) * r0, w01 = lrelu_exp(l0.y + ad.y) * r1;
        float w10 = lrelu_exp(l1.x + ad.x) * r0, w11 = lrelu_exp(l1.y + ad.y) * r1;
        float w20 = lrelu_exp(l2.x + ad.x) * r0, w21 = lrelu_exp(l2.y + ad.y) * r1;
        float w30 = lrelu_exp(l3.x + ad.x) * r0, w31 = lrelu_exp(l3.y + ad.y) * r1;
        a0.x = fmaf(w00, h00.x, a0.x); a0.y = fmaf(w00, h00.y, a0.y); a0.z = fmaf(w00, h00.z, a0.z); a0.w = fmaf(w00, h00.w, a0.w);
        a1.x = fmaf(w01, h01.x, a1.x); a1.y = fmaf(w01, h01.y, a1.y); a1.z = fmaf(w01, h01.z, a1.z); a1.w = fmaf(w01, h01.w, a1.w);
        c0.x = fmaf(w10, h10.x, c0.x); c0.y = fmaf(w10, h10.y, c0.y); c0.z = fmaf(w10, h10.z, c0.z); c0.w = fmaf(w10, h10.w, c0.w);
        c1.x = fmaf(w11, h11.x, c1.x); c1.y = fmaf(w11, h11.y, c1.y); c1.z = fmaf(w11, h11.z, c1.z); c1.w = fmaf(w11, h11.w, c1.w);
        a0.x = fmaf(w20, h20.x, a0.x); a0.y = fmaf(w20, h20.y, a0.y); a0.z = fmaf(w20, h20.z, a0.z); a0.w = fmaf(w20, h20.w, a0.w);
        a1.x = fmaf(w21, h21.x, a1.x); a1.y = fmaf(w21, h21.y, a1.y); a1.z = fmaf(w21, h21.z, a1.z); a1.w = fmaf(w21, h21.w, a1.w);
        c0.x = fmaf(w30, h30.x, c0.x); c0.y = fmaf(w30, h30.y, c0.y); c0.z = fmaf(w30, h30.z, c0.z); c0.w = fmaf(w30, h30.w, c0.w);
        c1.x = fmaf(w31, h31.x, c1.x); c1.y = fmaf(w31, h31.y, c1.y); c1.z = fmaf(w31, h31.z, c1.z); c1.w = fmaf(w31, h31.w, c1.w);
    }
    for (; e < end; e++) {
        int src = g_csr_src[e];
        float2 s = *(const float2*)&g_alS1[src * 4 + hp * 2];
        float w0 = lrelu_exp(s.x + ad.x) * r0;
        float w1 = lrelu_exp(s.y + ad.y) * r1;
        const float4* p = (const float4*)&g_h1[(size_t)src * F1 + colBase];
        float4 h0 = p[lane], h1 = p[32 + lane];
        a0.x = fmaf(w0, h0.x, a0.x); a0.y = fmaf(w0, h0.y, a0.y); a0.z = fmaf(w0, h0.z, a0.z); a0.w = fmaf(w0, h0.w, a0.w);
        a1.x = fmaf(w1, h1.x, a1.x); a1.y = fmaf(w1, h1.y, a1.y); a1.z = fmaf(w1, h1.z, a1.z); a1.w = fmaf(w1, h1.w, a1.w);
    }
    a0.x += c0.x; a0.y += c0.y; a0.z += c0.z; a0.w += c0.w;
    a1.x += c1.x; a1.y += c1.y; a1.z += c1.z; a1.w += c1.w;

    // bias + ELU + store (2 heads)
    float* outp = &g_agg1[(size_t)n * F1 + colBase];
    float4 acc2[2] = { a0, a1 };
    #pragma unroll
    for (int h = 0; h < 2; h++) {
        float4 bb = *(const float4*)&b1[(hp * 2 + h) * HID + lane * 4];
        float4 v = acc2[h];
        v.x += bb.x; v.y += bb.y; v.z += bb.z; v.w += bb.w;
        v.x = v.x > 0.f ? v.x : expm1f(v.x);
        v.y = v.y > 0.f ? v.y : expm1f(v.y);
        v.z = v.z > 0.f ? v.z : expm1f(v.z);
        v.w = v.w > 0.f ? v.w : expm1f(v.w);
        *(float4*)&outp[h * HID + lane * 4] = v;
    }
}

// ======= layer 2 fused softmax + aggregate + bias -> outZ (2-edge unroll) =======
__global__ __launch_bounds__(256)
void k_agg2(const float* __restrict__ b2, float* __restrict__ outZ) {
    int warp = (blockIdx.x * blockDim.x + threadIdx.x) >> 5;
    int lane = threadIdx.x & 31;
    if (warp >= N_NODES) return;
    int n = warp;
    int beg = g_rowptr[n], end = g_rowptr[n + 1];
    float ad = g_alD2[n];

    float den = 0.f;
    for (int e = beg + lane; e < end; e += 32) {
        int src = g_csr_src[e];
        den += lrelu_exp(g_alS2[src] + ad);
    }
    #pragma unroll
    for (int o = 16; o > 0; o >>= 1) den += __shfl_xor_sync(0xffffffffu, den, o);
    float rden = 1.f / den;

    float accA = 0.f, accB = 0.f;
    int e = beg;
    for (; e + 2 <= end; e += 2) {
        int s0 = g_csr_src[e], s1 = g_csr_src[e + 1];
        float alpha0 = lrelu_exp(g_alS2[s0] + ad) * rden;
        float alpha1 = lrelu_exp(g_alS2[s1] + ad) * rden;
        if (lane < OUT_CH) {
            float z0 = g_zpre32[(size_t)s0 * ZP + lane];
            float z1 = g_zpre32[(size_t)s1 * ZP + lane];
            accA = fmaf(alpha0, z0, accA);
            accB = fmaf(alpha1, z1, accB);
        }
    }
    if (e < end) {
        int src = g_csr_src[e];
        float alpha = lrelu_exp(g_alS2[src] + ad) * rden;
        if (lane < OUT_CH) accA = fmaf(alpha, g_zpre32[(size_t)src * ZP + lane], accA);
    }
    if (lane < OUT_CH) outZ[n * OUT_CH + lane] = accA + accB + b2[lane];
}

// ================= decoder tiled =================
#define DBN 64
__global__ __launch_bounds__(256, 2)
void k_decodert(const float* __restrict__ Wd, const float* __restrict__ bd,
                float* __restrict__ out, const float* __restrict__ z) {
    __shared__ float As[32][BM + 4];
    __shared__ float Bs[32][DBN];
    const int tid = threadIdx.x;
    const int tr = tid >> 4;
    const int tc = tid & 15;
    const int rowBase = blockIdx.y * BM;
    const int colBase = blockIdx.x * DBN;

    for (int idx = tid; idx < BM * 32; idx += 256) {
        int r = idx >> 5;
        int k = idx & 31;
        int gr = rowBase + r;
        float v = 0.f;
        if (k < OUT_CH && gr < N_NODES) v = z[(size_t)gr * OUT_CH + k];
        As[k][r] = v;
    }
    for (int idx = tid; idx < 32 * DBN; idx += 256) {
        int k = idx >> 6;
        int c = idx & 63;
        Bs[k][c] = (k < OUT_CH) ? Wd[(size_t)k * IN_CH + colBase + c] : 0.f;
    }
    __syncthreads();

    float acc[8][4];
    {
        float4 bb = *(const float4*)&bd[colBase + tc * 4];
        #pragma unroll
        for (int i = 0; i < 8; i++) {
            acc[i][0] = bb.x; acc[i][1] = bb.y; acc[i][2] = bb.z; acc[i][3] = bb.w;
        }
    }
    #pragma unroll
    for (int k = 0; k < OUT_CH; k++) {
        float a[8], b[4];
        #pragma unroll
        for (int i = 0; i < 8; i += 4)
            *(float4*)&a[i] = *(const float4*)&As[k][tr * 8 + i];
        *(float4*)&b[0] = *(const float4*)&Bs[k][tc * 4];
        #pragma unroll
        for (int i = 0; i < 8; i++)
            #pragma unroll
            for (int j = 0; j < 4; j++) acc[i][j] = fmaf(a[i], b[j], acc[i][j]);
    }
    #pragma unroll
    for (int i = 0; i < 8; i++) {
        int gr = rowBase + tr * 8 + i;
        if (gr >= N_NODES) continue;
        *(float4*)&out[(size_t)gr * IN_CH + colBase + tc * 4] = *(float4*)&acc[i][0];
    }
}

extern "C" void kernel_launch(void* const* d_in, const int* in_sizes, int n_in,
                              void* d_out, int out_size) {
    const float* x   = (const float*)d_in[0];
    const int*   ei  = (const int*)d_in[1];
    const float* W1  = (const float*)d_in[2];
    const float* aS1 = (const float*)d_in[3];
    const float* aD1 = (const float*)d_in[4];
    const float* b1  = (const float*)d_in[5];
    const float* W2  = (const float*)d_in[6];
    const float* aS2 = (const float*)d_in[7];
    const float* aD2 = (const float*)d_in[8];
    const float* b2  = (const float*)d_in[9];
    const float* Wd  = (const float*)d_in[10];
    const float* bd  = (const float*)d_in[11];
    (void)in_sizes; (void)n_in; (void)out_size;

    float* out  = (float*)d_out;
    float* outZ = out + (size_t)N_NODES * IN_CH;

    static cudaStream_t s2 = nullptr;
    static cudaEvent_t evFork = nullptr, evJoin = nullptr;
    if (s2 == nullptr) {
        cudaStreamCreateWithFlags(&s2, cudaStreamNonBlocking);
        cudaEventCreateWithFlags(&evFork, cudaEventDisableTiming);
        cudaEventCreateWithFlags(&evJoin, cudaEventDisableTiming);
    }

    cudaEventRecord(evFork, 0);
    cudaStreamWaitEvent(s2, evFork, 0);
    k_zero_rowptr<<<(N_NODES + 1 + 255) / 256, 256, 0, s2>>>();
    k_count<<<(ET + 255) / 256, 256, 0, s2>>>(ei);
    k_scan<<<1, 1024, 0, s2>>>();
    k_scatter<<<(ET + 255) / 256, 256, 0, s2>>>(ei);
    cudaEventRecord(evJoin, s2);

    {
        dim3 grid(F1 / BN1, M_PAD / BM);
        k_gemm_tf32<<<grid, 256>>>(x, W1);
    }
    k_logits1<<<N_NODES, 128>>>(aS1, aD1);

    cudaStreamWaitEvent(0, evJoin, 0);

    k_agg1<<<(2 * N_NODES * 32 + 255) / 256, 256>>>(b1);

    k_gemm2_tf32<<<M_PAD / BM, 256>>>(W2);
    k_logits2<<<(N_NODES * 32 + 255) / 256, 256>>>(aS2, aD2);
    k_agg2<<<(N_NODES * 32 + 255) / 256, 256>>>(b2, outZ);

    {
        dim3 grid(IN_CH / DBN, (N_NODES + BM - 1) / BM);
        k_decodert<<<grid, 256>>>(Wd, bd, out, outZ);
    }
}

// round 15
// speedup vs baseline: 2.0038x; 1.0379x over previous
#include <cuda_runtime.h>
#include <cuda_fp16.h>
#include <cstdint>
#include <float.h>
#include <mma.h>

using namespace nvcuda;

#define N_NODES 20000
#define N_EDGES 320000
#define ET      340000
#define IN_CH   512
#define HID     128
#define HEADS   4
#define F1      512
#define OUT_CH  30
#define NEG_SLOPE 0.2f

#define M_PAD 20096
#define ZP    32

__device__ __half g_h1h[M_PAD * F1];   // h1 stored fp16 (gather traffic halved)
__device__ float g_agg1[N_NODES * F1];
__device__ float g_alS1[N_NODES * HEADS];
__device__ float g_alD1[N_NODES * HEADS];
__device__ float g_zpre32[M_PAD * ZP];
__device__ float g_alS2[N_NODES];
__device__ float g_alD2[N_NODES];
__device__ int   g_rowptr[N_NODES + 1];
__device__ int   g_cursor[N_NODES];
__device__ int   g_csr_src[ET];

__device__ __forceinline__ void edge_endpoints(int e, const int* __restrict__ ei,
                                               int& src, int& dst) {
    if (e < N_EDGES) { src = ei[e]; dst = ei[N_EDGES + e]; }
    else { src = e - N_EDGES; dst = src; }
}

__device__ __forceinline__ float lrelu_exp(float v) {
    return __expf(v > 0.f ? v : NEG_SLOPE * v);
}

// load 4 consecutive fp16 (8 bytes) and widen to float4
__device__ __forceinline__ float4 ldhf4(const __half2* p) {
    float2 raw = *(const float2*)p;
    __half2* h = (__half2*)&raw;
    float2 u0 = __half22float2(h[0]);
    float2 u1 = __half22float2(h[1]);
    return make_float4(u0.x, u0.y, u1.x, u1.y);
}

// ================= CSR build =================
__global__ void k_zero_rowptr() {
    int i = blockIdx.x * blockDim.x + threadIdx.x;
    if (i <= N_NODES) g_rowptr[i] = 0;
}
__global__ void k_count(const int* __restrict__ ei) {
    int e = blockIdx.x * blockDim.x + threadIdx.x;
    if (e >= ET) return;
    int src, dst; edge_endpoints(e, ei, src, dst);
    (void)src;
    atomicAdd(&g_rowptr[dst + 1], 1);
}
#define SCAN_CH 20
__global__ __launch_bounds__(1024)
void k_scan() {
    __shared__ int wsum[32];
    int tid = threadIdx.x;
    int lane = tid & 31, warp = tid >> 5;
    int base = tid * SCAN_CH;
    int incl[SCAN_CH];
    int run = 0;
    #pragma unroll
    for (int i = 0; i < SCAN_CH; i++) {
        int idx = base + i;
        int v = (idx <= N_NODES) ? g_rowptr[idx] : 0;
        run += v;
        incl[i] = run;
    }
    int ws = run;
    #pragma unroll
    for (int o = 1; o < 32; o <<= 1) {
        int t = __shfl_up_sync(0xffffffffu, ws, o);
        if (lane >= o) ws += t;
    }
    if (lane == 31) wsum[warp] = ws;
    __syncthreads();
    if (warp == 0) {
        int t = (lane < 32) ? wsum[lane] : 0;
        #pragma unroll
        for (int o = 1; o < 32; o <<= 1) {
            int u = __shfl_up_sync(0xffffffffu, t, o);
            if (lane >= o) t += u;
        }
        wsum[lane] = t;
    }
    __syncthreads();
    int offset = (ws - run) + (warp > 0 ? wsum[warp - 1] : 0);
    #pragma unroll
    for (int i = 0; i < SCAN_CH; i++) {
        int idx = base + i;
        if (idx <= N_NODES) {
            int out = incl[i] + offset;
            g_rowptr[idx] = out;
            if (idx < N_NODES) g_cursor[idx] = out;
        }
    }
}
__global__ void k_scatter(const int* __restrict__ ei) {
    int e = blockIdx.x * blockDim.x + threadIdx.x;
    if (e >= ET) return;
    int src, dst; edge_endpoints(e, ei, src, dst);
    int pos = atomicAdd(&g_cursor[dst], 1);
    g_csr_src[pos] = src;
}

// ========== GEMM1 (tf32): g_h1h = fp16(x @ W1), 128x128 tile, prefetch ==========
#define BM 128
#define BN1 128
#define BK 16
#define LDA (BK + 4)
#define LDB1 (BN1 + 4)
#define LDSC 20   // epilogue staging ld — multiple of 4 (float fragment requirement)
__global__ __launch_bounds__(256, 2)
void k_gemm_tf32(const float* __restrict__ A, const float* __restrict__ B) {
    __shared__ float As[BM][LDA];
    __shared__ float Bs[BK][LDB1];
    __shared__ float sc[8][16][LDSC];
    const int tid = threadIdx.x;
    const int wid = tid >> 5;
    const int lane = tid & 31;
    const int wm = wid >> 1;
    const int wn = wid & 1;
    const int rowBase = blockIdx.y * BM;
    const int colBase = blockIdx.x * BN1;

    wmma::fragment<wmma::accumulator, 16, 16, 8, float> acc[2][4];
    #pragma unroll
    for (int i = 0; i < 2; i++)
        #pragma unroll
        for (int j = 0; j < 4; j++) wmma::fill_fragment(acc[i][j], 0.f);

    float4 pa[2], pb[2];
    #pragma unroll
    for (int t = 0; t < 2; t++) {
        int idx = tid * 2 + t;
        int r = idx >> 2, c = (idx & 3) * 4;
        int gr = rowBase + r;
        pa[t] = (gr < N_NODES) ? *(const float4*)&A[(size_t)gr * IN_CH + c]
                               : make_float4(0.f, 0.f, 0.f, 0.f);
        int br = idx >> 5, bc = (idx & 31) * 4;
        pb[t] = *(const float4*)&B[(size_t)br * F1 + colBase + bc];
    }

    const int T = IN_CH / BK;
    for (int t0 = 0; t0 < T; t0++) {
        #pragma unroll
        for (int t = 0; t < 2; t++) {
            int idx = tid * 2 + t;
            int r = idx >> 2, c = (idx & 3) * 4;
            As[r][c + 0] = wmma::__float_to_tf32(pa[t].x);
            As[r][c + 1] = wmma::__float_to_tf32(pa[t].y);
            As[r][c + 2] = wmma::__float_to_tf32(pa[t].z);
            As[r][c + 3] = wmma::__float_to_tf32(pa[t].w);
            int br = idx >> 5, bc = (idx & 31) * 4;
            Bs[br][bc + 0] = wmma::__float_to_tf32(pb[t].x);
            Bs[br][bc + 1] = wmma::__float_to_tf32(pb[t].y);
            Bs[br][bc + 2] = wmma::__float_to_tf32(pb[t].z);
            Bs[br][bc + 3] = wmma::__float_to_tf32(pb[t].w);
        }
        __syncthreads();
        if (t0 + 1 < T) {
            int k0n = (t0 + 1) * BK;
            #pragma unroll
            for (int t = 0; t < 2; t++) {
                int idx = tid * 2 + t;
                int r = idx >> 2, c = (idx & 3) * 4;
                int gr = rowBase + r;
                pa[t] = (gr < N_NODES) ? *(const float4*)&A[(size_t)gr * IN_CH + k0n + c]
                                       : make_float4(0.f, 0.f, 0.f, 0.f);
                int br = idx >> 5, bc = (idx & 31) * 4;
                pb[t] = *(const float4*)&B[(size_t)(k0n + br) * F1 + colBase + bc];
            }
        }
        #pragma unroll
        for (int kk = 0; kk < BK; kk += 8) {
            wmma::fragment<wmma::matrix_a, 16, 16, 8, wmma::precision::tf32, wmma::row_major> fa[2];
            wmma::fragment<wmma::matrix_b, 16, 16, 8, wmma::precision::tf32, wmma::row_major> fb[4];
            #pragma unroll
            for (int i = 0; i < 2; i++)
                wmma::load_matrix_sync(fa[i], &As[wm * 32 + i * 16][kk], LDA);
            #pragma unroll
            for (int j = 0; j < 4; j++)
                wmma::load_matrix_sync(fb[j], &Bs[kk][wn * 64 + j * 16], LDB1);
            #pragma unroll
            for (int i = 0; i < 2; i++)
                #pragma unroll
                for (int j = 0; j < 4; j++)
                    wmma::mma_sync(acc[i][j], fa[i], fb[j], acc[i][j]);
        }
        __syncthreads();
    }
    // epilogue: fragment -> smem (ldm=20) -> fp16 global
    #pragma unroll
    for (int i = 0; i < 2; i++)
        #pragma unroll
        for (int j = 0; j < 4; j++) {
            wmma::store_matrix_sync(&sc[wid][0][0], acc[i][j], LDSC, wmma::mem_row_major);
            __syncwarp();
            int r = rowBase + wm * 32 + i * 16 + (lane >> 1);
            int c = colBase + wn * 64 + j * 16 + (lane & 1) * 8;
            const float* srow = &sc[wid][lane >> 1][(lane & 1) * 8];
            __half2 o[4];
            o[0] = __floats2half2_rn(srow[0], srow[1]);
            o[1] = __floats2half2_rn(srow[2], srow[3]);
            o[2] = __floats2half2_rn(srow[4], srow[5]);
            o[3] = __floats2half2_rn(srow[6], srow[7]);
            *(float4*)&g_h1h[(size_t)r * F1 + c] = *(float4*)o;
            __syncwarp();
        }
}

// ========== GEMM2 (tf32): g_zpre32 = agg1 @ W2pad ==========
#define BN2 32
#define LDB2 (BN2 + 4)
__global__ __launch_bounds__(256, 2)
void k_gemm2_tf32(const float* __restrict__ W2) {
    __shared__ float As[BM][LDA];
    __shared__ float Bs[BK][LDB2];
    const int tid = threadIdx.x;
    const int wid = tid >> 5;
    const int wm = wid >> 1;
    const int wn = wid & 1;
    const int rowBase = blockIdx.x * BM;

    wmma::fragment<wmma::accumulator, 16, 16, 8, float> acc[2];
    wmma::fill_fragment(acc[0], 0.f);
    wmma::fill_fragment(acc[1], 0.f);

    for (int k0 = 0; k0 < F1; k0 += BK) {
        #pragma unroll
        for (int t = 0; t < 2; t++) {
            int idx = tid * 2 + t;
            int r = idx >> 2;
            int c = (idx & 3) * 4;
            int gr = rowBase + r;
            float4 v = make_float4(0.f, 0.f, 0.f, 0.f);
            if (gr < N_NODES) v = *(const float4*)&g_agg1[(size_t)gr * F1 + k0 + c];
            As[r][c + 0] = wmma::__float_to_tf32(v.x);
            As[r][c + 1] = wmma::__float_to_tf32(v.y);
            As[r][c + 2] = wmma::__float_to_tf32(v.z);
            As[r][c + 3] = wmma::__float_to_tf32(v.w);
        }
        {
            #pragma unroll
            for (int t = 0; t < 2; t++) {
                int idx = tid * 2 + t;
                int r = idx >> 5;
                int c = idx & 31;
                float v = (c < OUT_CH) ? W2[(size_t)(k0 + r) * OUT_CH + c] : 0.f;
                Bs[r][c] = wmma::__float_to_tf32(v);
            }
        }
        __syncthreads();
        #pragma unroll
        for (int kk = 0; kk < BK; kk += 8) {
            wmma::fragment<wmma::matrix_a, 16, 16, 8, wmma::precision::tf32, wmma::row_major> fa[2];
            wmma::fragment<wmma::matrix_b, 16, 16, 8, wmma::precision::tf32, wmma::row_major> fb;
            #pragma unroll
            for (int i = 0; i < 2; i++)
                wmma::load_matrix_sync(fa[i], &As[wm * 32 + i * 16][kk], LDA);
            wmma::load_matrix_sync(fb, &Bs[kk][wn * 16], LDB2);
            #pragma unroll
            for (int i = 0; i < 2; i++)
                wmma::mma_sync(acc[i], fa[i], fb, acc[i]);
        }
        __syncthreads();
    }
    #pragma unroll
    for (int i = 0; i < 2; i++) {
        int r = rowBase + wm * 32 + i * 16;
        int c = wn * 16;
        wmma::store_matrix_sync(&g_zpre32[(size_t)r * ZP + c], acc[i], ZP,
                                wmma::mem_row_major);
    }
}

// ================= logits2: warp per node =================
__global__ __launch_bounds__(256)
void k_logits2(const float* __restrict__ aS2, const float* __restrict__ aD2) {
    int warp = (blockIdx.x * blockDim.x + threadIdx.x) >> 5;
    int lane = threadIdx.x & 31;
    if (warp >= N_NODES) return;
    float z = (lane < OUT_CH) ? g_zpre32[(size_t)warp * ZP + lane] : 0.f;
    float ps = (lane < OUT_CH) ? z * aS2[lane] : 0.f;
    float pd = (lane < OUT_CH) ? z * aD2[lane] : 0.f;
    #pragma unroll
    for (int o = 16; o > 0; o >>= 1) {
        ps += __shfl_down_sync(0xffffffffu, ps, o);
        pd += __shfl_down_sync(0xffffffffu, pd, o);
    }
    if (lane == 0) { g_alS2[warp] = ps; g_alD2[warp] = pd; }
}

// ================= layer 1 attention logits per node (fp16 h1) =================
__global__ void k_logits1(const float* __restrict__ aS, const float* __restrict__ aD) {
    int n = blockIdx.x;
    int w = threadIdx.x >> 5, lane = threadIdx.x & 31;
    const __half2* hr = (const __half2*)&g_h1h[(size_t)n * F1 + w * HID];
    const float* av = aS + w * HID;
    const float* dv = aD + w * HID;
    float4 h = ldhf4(hr + lane * 2);
    float4 a = *(const float4*)&av[lane * 4];
    float4 d4 = *(const float4*)&dv[lane * 4];
    float s = h.x * a.x + h.y * a.y + h.z * a.z + h.w * a.w;
    float d = h.x * d4.x + h.y * d4.y + h.z * d4.z + h.w * d4.w;
    #pragma unroll
    for (int o = 16; o > 0; o >>= 1) {
        s += __shfl_down_sync(0xffffffffu, s, o);
        d += __shfl_down_sync(0xffffffffu, d, o);
    }
    if (lane == 0) { g_alS1[n * HEADS + w] = s; g_alD1[n * HEADS + w] = d; }
}

// ======= layer 1 aggregate: warp per (node, head-pair), 4-edge unroll, fp16 gather =======
__global__ __launch_bounds__(256)
void k_agg1(const float* __restrict__ b1) {
    int gw = (blockIdx.x * blockDim.x + threadIdx.x) >> 5;
    int lane = threadIdx.x & 31;
    if (gw >= 2 * N_NODES) return;
    int n = gw >> 1;
    int hp = gw & 1;
    int beg = g_rowptr[n], end = g_rowptr[n + 1];
    float2 ad = *(const float2*)&g_alD1[n * 4 + hp * 2];

    float2 den = make_float2(0.f, 0.f);
    for (int e = beg + lane; e < end; e += 32) {
        int src = g_csr_src[e];
        float2 s = *(const float2*)&g_alS1[src * 4 + hp * 2];
        den.x += lrelu_exp(s.x + ad.x);
        den.y += lrelu_exp(s.y + ad.y);
    }
    #pragma unroll
    for (int o = 16; o > 0; o >>= 1) {
        den.x += __shfl_xor_sync(0xffffffffu, den.x, o);
        den.y += __shfl_xor_sync(0xffffffffu, den.y, o);
    }
    float r0 = 1.f / den.x, r1 = 1.f / den.y;

    const size_t colBase = (size_t)(hp * 2) * HID;

    float4 a0 = make_float4(0.f, 0.f, 0.f, 0.f), a1 = a0;
    float4 c0 = a0, c1 = a0;
    int e = beg;
    for (; e + 4 <= end; e += 4) {
        int s0 = g_csr_src[e], s1 = g_csr_src[e + 1];
        int s2 = g_csr_src[e + 2], s3 = g_csr_src[e + 3];
        float2 l0 = *(const float2*)&g_alS1[s0 * 4 + hp * 2];
        float2 l1 = *(const float2*)&g_alS1[s1 * 4 + hp * 2];
        float2 l2 = *(const float2*)&g_alS1[s2 * 4 + hp * 2];
        float2 l3 = *(const float2*)&g_alS1[s3 * 4 + hp * 2];
        const __half2* p0 = (const __half2*)&g_h1h[(size_t)s0 * F1 + colBase];
        const __half2* p1 = (const __half2*)&g_h1h[(size_t)s1 * F1 + colBase];
        const __half2* p2 = (const __half2*)&g_h1h[(size_t)s2 * F1 + colBase];
        const __half2* p3 = (const __half2*)&g_h1h[(size_t)s3 * F1 + colBase];
        float4 h00 = ldhf4(p0 + lane * 2), h01 = ldhf4(p0 + 64 + lane * 2);
        float4 h10 = ldhf4(p1 + lane * 2), h11 = ldhf4(p1 + 64 + lane * 2);
        float4 h20 = ldhf4(p2 + lane * 2), h21 = ldhf4(p2 + 64 + lane * 2);
        float4 h30 = ldhf4(p3 + lane * 2), h31 = ldhf4(p3 + 64 + lane * 2);
        float w00 = lrelu_exp(l0.x + ad.x) * r0, w01 = lrelu_exp(l0.y + ad.y) * r1;
        float w10 = lrelu_exp(l1.x + ad.x) * r0, w11 = lrelu_exp(l1.y + ad.y) * r1;
        float w20 = lrelu_exp(l2.x + ad.x) * r0, w21 = lrelu_exp(l2.y + ad.y) * r1;
        float w30 = lrelu_exp(l3.x + ad.x) * r0, w31 = lrelu_exp(l3.y + ad.y) * r1;
        a0.x = fmaf(w00, h00.x, a0.x); a0.y = fmaf(w00, h00.y, a0.y); a0.z = fmaf(w00, h00.z, a0.z); a0.w = fmaf(w00, h00.w, a0.w);
        a1.x = fmaf(w01, h01.x, a1.x); a1.y = fmaf(w01, h01.y, a1.y); a1.z = fmaf(w01, h01.z, a1.z); a1.w = fmaf(w01, h01.w, a1.w);
        c0.x = fmaf(w10, h10.x, c0.x); c0.y = fmaf(w10, h10.y, c0.y); c0.z = fmaf(w10, h10.z, c0.z); c0.w = fmaf(w10, h10.w, c0.w);
        c1.x = fmaf(w11, h11.x, c1.x); c1.y = fmaf(w11, h11.y, c1.y); c1.z = fmaf(w11, h11.z, c1.z); c1.w = fmaf(w11, h11.w, c1.w);
        a0.x = fmaf(w20, h20.x, a0.x); a0.y = fmaf(w20, h20.y, a0.y); a0.z = fmaf(w20, h20.z, a0.z); a0.w = fmaf(w20, h20.w, a0.w);
        a1.x = fmaf(w21, h21.x, a1.x); a1.y = fmaf(w21, h21.y, a1.y); a1.z = fmaf(w21, h21.z, a1.z); a1.w = fmaf(w21, h21.w, a1.w);
        c0.x = fmaf(w30, h30.x, c0.x); c0.y = fmaf(w30, h30.y, c0.y); c0.z = fmaf(w30, h30.z, c0.z); c0.w = fmaf(w30, h30.w, c0.w);
        c1.x = fmaf(w31, h31.x, c1.x); c1.y = fmaf(w31, h31.y, c1.y); c1.z = fmaf(w31, h31.z, c1.z); c1.w = fmaf(w31, h31.w, c1.w);
    }
    for (; e < end; e++) {
        int src = g_csr_src[e];
        float2 s = *(const float2*)&g_alS1[src * 4 + hp * 2];
        float w0 = lrelu_exp(s.x + ad.x) * r0;
        float w1 = lrelu_exp(s.y + ad.y) * r1;
        const __half2* p = (const __half2*)&g_h1h[(size_t)src * F1 + colBase];
        float4 h0 = ldhf4(p + lane * 2), h1 = ldhf4(p + 64 + lane * 2);
        a0.x = fmaf(w0, h0.x, a0.x); a0.y = fmaf(w0, h0.y, a0.y); a0.z = fmaf(w0, h0.z, a0.z); a0.w = fmaf(w0, h0.w, a0.w);
        a1.x = fmaf(w1, h1.x, a1.x); a1.y = fmaf(w1, h1.y, a1.y); a1.z = fmaf(w1, h1.z, a1.z); a1.w = fmaf(w1, h1.w, a1.w);
    }
    a0.x += c0.x; a0.y += c0.y; a0.z += c0.z; a0.w += c0.w;
    a1.x += c1.x; a1.y += c1.y; a1.z += c1.z; a1.w += c1.w;

    float* outp = &g_agg1[(size_t)n * F1 + colBase];
    float4 acc2[2] = { a0, a1 };
    #pragma unroll
    for (int h = 0; h < 2; h++) {
        float4 bb = *(const float4*)&b1[(hp * 2 + h) * HID + lane * 4];
        float4 v = acc2[h];
        v.x += bb.x; v.y += bb.y; v.z += bb.z; v.w += bb.w;
        v.x = v.x > 0.f ? v.x : expm1f(v.x);
        v.y = v.y > 0.f ? v.y : expm1f(v.y);
        v.z = v.z > 0.f ? v.z : expm1f(v.z);
        v.w = v.w > 0.f ? v.w : expm1f(v.w);
        *(float4*)&outp[h * HID + lane * 4] = v;
    }
}

// ======= layer 2 fused softmax + aggregate + bias -> outZ (2-edge unroll) =======
__global__ __launch_bounds__(256)
void k_agg2(const float* __restrict__ b2, float* __restrict__ outZ) {
    int warp = (blockIdx.x * blockDim.x + threadIdx.x) >> 5;
    int lane = threadIdx.x & 31;
    if (warp >= N_NODES) return;
    int n = warp;
    int beg = g_rowptr[n], end = g_rowptr[n + 1];
    float ad = g_alD2[n];

    float den = 0.f;
    for (int e = beg + lane; e < end; e += 32) {
        int src = g_csr_src[e];
        den += lrelu_exp(g_alS2[src] + ad);
    }
    #pragma unroll
    for (int o = 16; o > 0; o >>= 1) den += __shfl_xor_sync(0xffffffffu, den, o);
    float rden = 1.f / den;

    float accA = 0.f, accB = 0.f;
    int e = beg;
    for (; e + 2 <= end; e += 2) {
        int s0 = g_csr_src[e], s1 = g_csr_src[e + 1];
        float alpha0 = lrelu_exp(g_alS2[s0] + ad) * rden;
        float alpha1 = lrelu_exp(g_alS2[s1] + ad) * rden;
        if (lane < OUT_CH) {
            float z0 = g_zpre32[(size_t)s0 * ZP + lane];
            float z1 = g_zpre32[(size_t)s1 * ZP + lane];
            accA = fmaf(alpha0, z0, accA);
            accB = fmaf(alpha1, z1, accB);
        }
    }
    if (e < end) {
        int src = g_csr_src[e];
        float alpha = lrelu_exp(g_alS2[src] + ad) * rden;
        if (lane < OUT_CH) accA = fmaf(alpha, g_zpre32[(size_t)src * ZP + lane], accA);
    }
    if (lane < OUT_CH) outZ[n * OUT_CH + lane] = accA + accB + b2[lane];
}

// ================= decoder tiled =================
#define DBN 64
__global__ __launch_bounds__(256, 2)
void k_decodert(const float* __restrict__ Wd, const float* __restrict__ bd,
                float* __restrict__ out, const float* __restrict__ z) {
    __shared__ float As[32][BM + 4];
    __shared__ float Bs[32][DBN];
    const int tid = threadIdx.x;
    const int tr = tid >> 4;
    const int tc = tid & 15;
    const int rowBase = blockIdx.y * BM;
    const int colBase = blockIdx.x * DBN;

    for (int idx = tid; idx < BM * 32; idx += 256) {
        int r = idx >> 5;
        int k = idx & 31;
        int gr = rowBase + r;
        float v = 0.f;
        if (k < OUT_CH && gr < N_NODES) v = z[(size_t)gr * OUT_CH + k];
        As[k][r] = v;
    }
    for (int idx = tid; idx < 32 * DBN; idx += 256) {
        int k = idx >> 6;
        int c = idx & 63;
        Bs[k][c] = (k < OUT_CH) ? Wd[(size_t)k * IN_CH + colBase + c] : 0.f;
    }
    __syncthreads();

    float acc[8][4];
    {
        float4 bb = *(const float4*)&bd[colBase + tc * 4];
        #pragma unroll
        for (int i = 0; i < 8; i++) {
            acc[i][0] = bb.x; acc[i][1] = bb.y; acc[i][2] = bb.z; acc[i][3] = bb.w;
        }
    }
    #pragma unroll
    for (int k = 0; k < OUT_CH; k++) {
        float a[8], b[4];
        #pragma unroll
        for (int i = 0; i < 8; i += 4)
            *(float4*)&a[i] = *(const float4*)&As[k][tr * 8 + i];
        *(float4*)&b[0] = *(const float4*)&Bs[k][tc * 4];
        #pragma unroll
        for (int i = 0; i < 8; i++)
            #pragma unroll
            for (int j = 0; j < 4; j++) acc[i][j] = fmaf(a[i], b[j], acc[i][j]);
    }
    #pragma unroll
    for (int i = 0; i < 8; i++) {
        int gr = rowBase + tr * 8 + i;
        if (gr >= N_NODES) continue;
        *(float4*)&out[(size_t)gr * IN_CH + colBase + tc * 4] = *(float4*)&acc[i][0];
    }
}

extern "C" void kernel_launch(void* const* d_in, const int* in_sizes, int n_in,
                              void* d_out, int out_size) {
    const float* x   = (const float*)d_in[0];
    const int*   ei  = (const int*)d_in[1];
    const float* W1  = (const float*)d_in[2];
    const float* aS1 = (const float*)d_in[3];
    const float* aD1 = (const float*)d_in[4];
    const float* b1  = (const float*)d_in[5];
    const float* W2  = (const float*)d_in[6];
    const float* aS2 = (const float*)d_in[7];
    const float* aD2 = (const float*)d_in[8];
    const float* b2  = (const float*)d_in[9];
    const float* Wd  = (const float*)d_in[10];
    const float* bd  = (const float*)d_in[11];
    (void)in_sizes; (void)n_in; (void)out_size;

    float* out  = (float*)d_out;
    float* outZ = out + (size_t)N_NODES * IN_CH;

    static cudaStream_t s2 = nullptr;
    static cudaEvent_t evFork = nullptr, evJoin = nullptr;
    if (s2 == nullptr) {
        cudaStreamCreateWithFlags(&s2, cudaStreamNonBlocking);
        cudaEventCreateWithFlags(&evFork, cudaEventDisableTiming);
        cudaEventCreateWithFlags(&evJoin, cudaEventDisableTiming);
    }

    cudaEventRecord(evFork, 0);
    cudaStreamWaitEvent(s2, evFork, 0);
    k_zero_rowptr<<<(N_NODES + 1 + 255) / 256, 256, 0, s2>>>();
    k_count<<<(ET + 255) / 256, 256, 0, s2>>>(ei);
    k_scan<<<1, 1024, 0, s2>>>();
    k_scatter<<<(ET + 255) / 256, 256, 0, s2>>>(ei);
    cudaEventRecord(evJoin, s2);

    {
        dim3 grid(F1 / BN1, M_PAD / BM);
        k_gemm_tf32<<<grid, 256>>>(x, W1);
    }
    k_logits1<<<N_NODES, 128>>>(aS1, aD1);

    cudaStreamWaitEvent(0, evJoin, 0);

    k_agg1<<<(2 * N_NODES * 32 + 255) / 256, 256>>>(b1);

    k_gemm2_tf32<<<M_PAD / BM, 256>>>(W2);
    k_logits2<<<(N_NODES * 32 + 255) / 256, 256>>>(aS2, aD2);
    k_agg2<<<(N_NODES * 32 + 255) / 256, 256>>>(b2, outZ);

    {
        dim3 grid(IN_CH / DBN, (N_NODES + BM - 1) / BM);
        k_decodert<<<grid, 256>>>(Wd, bd, out, outZ);
    }
}